// round 1
// baseline (speedup 1.0000x reference)
#include <cuda_runtime.h>
#include <math.h>

#define NN   100000
#define MM   12
#define ORIGF 92
#define NBRF 41
#define AA   64
#define A2   128
#define HH   128
#define NCONVL 3
#define NC0  1000
#define EPSL 1e-5f

// ---------------- scratch (device globals; no runtime allocation) ----------------
__device__ float  g_x[NN * AA];                 // current atom features   (25.6 MB)
__device__ float  g_c[NN * A2];                 // x @ W_central           (51.2 MB)
__device__ float  g_d[NN * A2];                 // x @ W_neighbor          (51.2 MB)
__device__ float  g_gated[(size_t)NN * MM * A2];// pre-BN gated features   (614 MB)
__device__ float  g_ns[NN * AA];                // summed gated messages   (25.6 MB)
__device__ double g_s1[A2], g_q1[A2];           // BN1 sum / sumsq
__device__ double g_s2[AA], g_q2[AA];           // BN2 sum / sumsq
__device__ float  g_scale1[A2], g_shift1[A2];
__device__ float  g_scale2[AA], g_shift2[AA];
__device__ float  g_crys[NC0 * AA];
__device__ int    g_cnt[NC0];

// ---------------- activations ----------------
__device__ __forceinline__ float sp_f(float x) {
    // softplus = max(x,0) + log1p(exp(-|x|)); fast intrinsics keep abs err ~4e-7
    return fmaxf(x, 0.f) + __logf(1.f + __expf(-fabsf(x)));
}
__device__ __forceinline__ float sg_f(float x) {
    return __fdividef(1.f, 1.f + __expf(-x));
}

// ---------------- generic small GEMM: out[N,O] = in[N,K] @ W[K,O] + b ----------------
// 128 threads; W column cached in registers; x rows broadcast from smem as float4.
template <int K, int O>
__global__ void gemm_kernel(const float* __restrict__ in, const float* __restrict__ W,
                            const float* __restrict__ bias, float* __restrict__ out,
                            int nrows)
{
    __shared__ __align__(16) float sx[64 * K];
    const int t = threadIdx.x;
    const int o = t % O;
    const int grp = t / O;              // 128/O groups split the 64 rows
    const int rpt = 64 / (128 / O);     // rows per thread

    float w[K];
#pragma unroll
    for (int k = 0; k < K; k++) w[k] = W[k * O + o];
    const float b = bias ? bias[o] : 0.f;

    const int row0 = blockIdx.x * 64;
    const int total4 = 64 * K / 4;
    for (int e = t; e < total4; e += 128) {
        const int r  = e / (K / 4);
        const int k4 = e % (K / 4);
        float4 v = make_float4(0.f, 0.f, 0.f, 0.f);
        const int rg = row0 + r;
        if (rg < nrows) v = *(((const float4*)(in + (size_t)rg * K)) + k4);
        *(((float4*)(sx + r * K)) + k4) = v;
    }
    __syncthreads();

    for (int rr = 0; rr < rpt; rr++) {
        const int r  = grp * rpt + rr;
        const int rg = row0 + r;
        float a0 = 0.f, a1 = 0.f, a2 = 0.f, a3 = 0.f;
#pragma unroll
        for (int k4 = 0; k4 < K / 4; k4++) {
            const float4 v = *(((const float4*)(sx + r * K)) + k4);
            a0 += v.x * w[4 * k4 + 0];
            a1 += v.y * w[4 * k4 + 1];
            a2 += v.z * w[4 * k4 + 2];
            a3 += v.w * w[4 * k4 + 3];
        }
        if (rg < nrows) out[(size_t)rg * O + o] = (a0 + a1) + (a2 + a3) + b;
    }
}

// ---------------- zero BN stats ----------------
__global__ void zero_stats_kernel() {
    const int t = threadIdx.x;
    if (t < A2) { g_s1[t] = 0.0; g_q1[t] = 0.0; }
    if (t < AA) { g_s2[t] = 0.0; g_q2[t] = 0.0; }
}

// ---------------- gated = c[n] + d[idx] + nbr_fea @ W_edge + b ; accumulate BN1 stats ----------------
// 128 threads (one output column each), 16 atoms per block, W_edge in registers.
__global__ void gated_kernel(const float* __restrict__ nbr_fea, const int* __restrict__ nbr_idx,
                             const float* __restrict__ W3, const float* __restrict__ bias)
{
    __shared__ __align__(16) float snf[MM * 44];
    __shared__ int sidx[MM];
    const int o = threadIdx.x;

    float w3[44];
#pragma unroll
    for (int f = 0; f < NBRF; f++) w3[f] = W3[f * A2 + o];
    w3[41] = w3[42] = w3[43] = 0.f;
    const float b = bias[o];

    if (o < MM) { snf[o * 44 + 41] = 0.f; snf[o * 44 + 42] = 0.f; snf[o * 44 + 43] = 0.f; }

    float s = 0.f, q = 0.f;
    const int atom0 = blockIdx.x * 16;

    for (int ai = 0; ai < 16; ai++) {
        const int n = atom0 + ai;
        // cooperative load of this atom's 12x41 edge features (contiguous)
        for (int e = o; e < MM * NBRF; e += 128) {
            const int m = e / NBRF, f = e % NBRF;
            snf[m * 44 + f] = nbr_fea[(size_t)n * (MM * NBRF) + e];
        }
        if (o < MM) sidx[o] = nbr_idx[n * MM + o];
        __syncthreads();

        const float c = g_c[(size_t)n * A2 + o];
        for (int m = 0; m < MM; m++) {
            float y0 = c + b + g_d[(size_t)sidx[m] * A2 + o];
            float y1 = 0.f, y2 = 0.f, y3 = 0.f;
#pragma unroll
            for (int f4 = 0; f4 < 11; f4++) {
                const float4 v = *((const float4*)(snf + m * 44) + f4);
                y0 += v.x * w3[4 * f4 + 0];
                y1 += v.y * w3[4 * f4 + 1];
                y2 += v.z * w3[4 * f4 + 2];
                y3 += v.w * w3[4 * f4 + 3];
            }
            const float y = (y0 + y1) + (y2 + y3);
            g_gated[((size_t)n * MM + m) * A2 + o] = y;
            s += y; q += y * y;
        }
        __syncthreads();
    }
    atomicAdd(&g_s1[o], (double)s);
    atomicAdd(&g_q1[o], (double)q);
}

__global__ void finalize1_kernel(const float* __restrict__ g1, const float* __restrict__ b1) {
    const int o = threadIdx.x;
    const double cnt = (double)NN * MM;
    const double mean = g_s1[o] / cnt;
    const double var  = g_q1[o] / cnt - mean * mean;
    const float scale = g1[o] * rsqrtf((float)var + EPSL);
    g_scale1[o] = scale;
    g_shift1[o] = b1[o] - (float)mean * scale;
}

// ---------------- normalize, sigmoid*softplus, sum over M ; accumulate BN2 stats ----------------
// 256 threads = 4 sets x 64 features, 64 atoms per block.
__global__ void gatesum_kernel() {
    __shared__ float rs[4][64], rq[4][64];
    const int t = threadIdx.x;
    const int a = t % 64, set = t / 64;
    const float scf = g_scale1[a],      shf = g_shift1[a];
    const float scc = g_scale1[64 + a], shc = g_shift1[64 + a];

    float s = 0.f, q = 0.f;
    const int base_atom = blockIdx.x * 64 + set * 16;
    for (int i = 0; i < 16; i++) {
        const int n = base_atom + i;
        if (n >= NN) break;
        float acc = 0.f;
#pragma unroll 4
        for (int m = 0; m < MM; m++) {
            const size_t gb = ((size_t)n * MM + m) * A2;
            const float yf = g_gated[gb + a]      * scf + shf;
            const float yc = g_gated[gb + 64 + a] * scc + shc;
            acc += sg_f(yf) * sp_f(yc);
        }
        g_ns[n * 64 + a] = acc;
        s += acc; q += acc * acc;
    }
    rs[set][a] = s; rq[set][a] = q;
    __syncthreads();
    if (set == 0) {
        const float ts = rs[0][a] + rs[1][a] + rs[2][a] + rs[3][a];
        const float tq = rq[0][a] + rq[1][a] + rq[2][a] + rq[3][a];
        atomicAdd(&g_s2[a], (double)ts);
        atomicAdd(&g_q2[a], (double)tq);
    }
}

__global__ void finalize2_kernel(const float* __restrict__ g2, const float* __restrict__ b2) {
    const int a = threadIdx.x;
    const double cnt = (double)NN;
    const double mean = g_s2[a] / cnt;
    const double var  = g_q2[a] / cnt - mean * mean;
    const float scale = g2[a] * rsqrtf((float)var + EPSL);
    g_scale2[a] = scale;
    g_shift2[a] = b2[a] - (float)mean * scale;
}

__global__ void update_kernel() {
    const int i = blockIdx.x * blockDim.x + threadIdx.x;
    if (i >= NN * AA) return;
    const int a = i & 63;
    const float v = g_x[i] + g_ns[i] * g_scale2[a] + g_shift2[a];
    g_x[i] = sp_f(v);
}

// ---------------- pooling + head ----------------
__global__ void zero_pool_kernel() {
    const int i = blockIdx.x * blockDim.x + threadIdx.x;
    if (i < NC0 * AA) g_crys[i] = 0.f;
    if (i < NC0)      g_cnt[i]  = 0;
}

__global__ void pool_kernel(const int* __restrict__ cidx) {
    const int i = blockIdx.x * blockDim.x + threadIdx.x;
    if (i >= NN * AA) return;
    const int n = i >> 6, a = i & 63;
    const int c = cidx[n];
    atomicAdd(&g_crys[c * 64 + a], g_x[i]);
    if (a == 0) atomicAdd(&g_cnt[c], 1);
}

__global__ void head_kernel(const float* __restrict__ fc_W, const float* __restrict__ fc_b,
                            const float* __restrict__ out_W, const float* __restrict__ out_b,
                            float* __restrict__ out)
{
    __shared__ float spm[64];
    __shared__ float red[128];
    const int c = blockIdx.x, t = threadIdx.x;
    if (t < 64) {
        const float m = g_crys[c * 64 + t] / (float)g_cnt[c];
        spm[t] = sp_f(m);
    }
    __syncthreads();
    float h = fc_b[t];
#pragma unroll
    for (int a = 0; a < 64; a++) h += spm[a] * fc_W[a * HH + t];
    red[t] = sp_f(h) * out_W[t];
    __syncthreads();
    for (int sft = 64; sft > 0; sft >>= 1) {
        if (t < sft) red[t] += red[t + sft];
        __syncthreads();
    }
    if (t == 0) out[c] = red[0] + out_b[0];
}

// ---------------- host orchestration ----------------
extern "C" void kernel_launch(void* const* d_in, const int* in_sizes, int n_in,
                              void* d_out, int out_size)
{
    const float* atom_fea = (const float*)d_in[0];
    const float* nbr_fea  = (const float*)d_in[1];
    const int*   nbr_idx  = (const int*)  d_in[2];
    const int*   cidx     = (const int*)  d_in[3];
    const float* emb_W    = (const float*)d_in[4];
    const float* emb_b    = (const float*)d_in[5];
    const float* conv_W   = (const float*)d_in[6];
    const float* conv_b   = (const float*)d_in[7];
    const float* bn1_g    = (const float*)d_in[8];
    const float* bn1_b    = (const float*)d_in[9];
    const float* bn2_g    = (const float*)d_in[10];
    const float* bn2_b    = (const float*)d_in[11];
    const float* fc_W     = (const float*)d_in[12];
    const float* fc_b     = (const float*)d_in[13];
    const float* out_W    = (const float*)d_in[14];
    const float* out_b    = (const float*)d_in[15];
    float* out = (float*)d_out;

    float *px, *pc, *pd;
    cudaGetSymbolAddress((void**)&px, g_x);
    cudaGetSymbolAddress((void**)&pc, g_c);
    cudaGetSymbolAddress((void**)&pd, g_d);

    const int gemmBlocks = (NN + 63) / 64;

    // embedding: x = atom_fea @ emb_W + emb_b
    gemm_kernel<ORIGF, AA><<<gemmBlocks, 128>>>(atom_fea, emb_W, emb_b, px, NN);

    for (int i = 0; i < NCONVL; i++) {
        const float* Wl = conv_W + (size_t)i * (2 * AA + NBRF) * A2;  // [169,128]
        zero_stats_kernel<<<1, 128>>>();
        gemm_kernel<AA, A2><<<gemmBlocks, 128>>>(px, Wl,             nullptr, pc, NN);
        gemm_kernel<AA, A2><<<gemmBlocks, 128>>>(px, Wl + 64 * A2,   nullptr, pd, NN);
        gated_kernel<<<NN / 16, 128>>>(nbr_fea, nbr_idx, Wl + 128 * A2, conv_b + i * A2);
        finalize1_kernel<<<1, A2>>>(bn1_g + i * A2, bn1_b + i * A2);
        gatesum_kernel<<<(NN + 63) / 64, 256>>>();
        finalize2_kernel<<<1, AA>>>(bn2_g + i * AA, bn2_b + i * AA);
        update_kernel<<<(NN * AA + 255) / 256, 256>>>();
    }

    zero_pool_kernel<<<(NC0 * AA + 255) / 256, 256>>>();
    pool_kernel<<<(NN * AA + 255) / 256, 256>>>(cidx);
    head_kernel<<<NC0, 128>>>(fc_W, fc_b, out_W, out_b, out);
}

// round 2
// speedup vs baseline: 1.2441x; 1.2441x over previous
#include <cuda_runtime.h>
#include <math.h>

#define NN   100000
#define MM   12
#define ORIGF 92
#define NBRF 41
#define AA   64
#define A2   128
#define HH   128
#define NCONVL 3
#define NC0  1000
#define EPSL 1e-5f

typedef unsigned long long ull;

// ---------------- scratch (device globals; no runtime allocation) ----------------
__device__ float  g_x[NN * AA];
__device__ float  g_c[NN * A2];
__device__ float  g_d[NN * A2];
__device__ float  g_gated[(size_t)NN * MM * A2];
__device__ float  g_ns[NN * AA];
__device__ double g_s1[A2], g_q1[A2];
__device__ double g_s2[AA], g_q2[AA];
__device__ float  g_scale1[A2], g_shift1[A2];
__device__ float  g_scale2[AA], g_shift2[AA];
__device__ float  g_crys[NC0 * AA];
__device__ int    g_cnt[NC0];

// ---------------- f32x2 packed helpers ----------------
__device__ __forceinline__ ull pack2(float lo, float hi) {
    ull r; asm("mov.b64 %0, {%1, %2};" : "=l"(r) : "f"(lo), "f"(hi)); return r;
}
__device__ __forceinline__ ull dup2(float v) { return pack2(v, v); }
__device__ __forceinline__ void fma2(ull& d, ull a, ull b) {
    asm("fma.rn.f32x2 %0, %1, %2, %0;" : "+l"(d) : "l"(a), "l"(b));
}
__device__ __forceinline__ float2 unpack2(ull v) {
    float2 f; asm("mov.b64 {%0, %1}, %2;" : "=f"(f.x), "=f"(f.y) : "l"(v)); return f;
}

// ---------------- activations ----------------
__device__ __forceinline__ float sp_f(float x) {
    return fmaxf(x, 0.f) + __logf(1.f + __expf(-fabsf(x)));
}
__device__ __forceinline__ float sg_f(float x) {
    return __fdividef(1.f, 1.f + __expf(-x));
}

// ---------------- small GEMM with packed-K FFMA2 ----------------
// out[N,O] = in[N,K] @ W[K,O] + b.  128 threads; 64 rows per block.
template <int K, int O>
__global__ void gemm2_kernel(const float* __restrict__ in, const float* __restrict__ W,
                             const float* __restrict__ bias, float* __restrict__ out,
                             int nrows)
{
    __shared__ __align__(16) float sx[64 * K];
    const int t = threadIdx.x;
    const int o = t % O;
    const int grp = t / O;
    const int rpt = (64 * O) / 128;

    ull w2[K / 2];
#pragma unroll
    for (int k2 = 0; k2 < K / 2; k2++)
        w2[k2] = pack2(W[(2 * k2) * O + o], W[(2 * k2 + 1) * O + o]);
    const float bb = bias ? bias[o] : 0.f;

    const int row0 = blockIdx.x * 64;
    const int total4 = 64 * K / 4;
    for (int e = t; e < total4; e += 128) {
        const int r  = e / (K / 4);
        const int k4 = e % (K / 4);
        float4 v = make_float4(0.f, 0.f, 0.f, 0.f);
        const int rg = row0 + r;
        if (rg < nrows) v = *(((const float4*)(in + (size_t)rg * K)) + k4);
        *(((float4*)(sx + r * K)) + k4) = v;
    }
    __syncthreads();

    for (int rr = 0; rr < rpt; rr++) {
        const int r  = grp * rpt + rr;
        const int rg = row0 + r;
        ull c0 = 0ULL, c1 = 0ULL;
#pragma unroll
        for (int k4 = 0; k4 < K / 4; k4++) {
            const ulonglong2 p = *(((const ulonglong2*)(sx + r * K)) + k4);
            fma2(c0, p.x, w2[2 * k4]);
            fma2(c1, p.y, w2[2 * k4 + 1]);
        }
        if (rg < nrows) {
            const float2 f0 = unpack2(c0), f1 = unpack2(c1);
            out[(size_t)rg * O + o] = (f0.x + f0.y) + (f1.x + f1.y) + bb;
        }
    }
}

// ---------------- zero BN stats ----------------
__global__ void zero_stats_kernel() {
    const int t = threadIdx.x;
    if (t < A2) { g_s1[t] = 0.0; g_q1[t] = 0.0; }
    if (t < AA) { g_s2[t] = 0.0; g_q2[t] = 0.0; }
}

// ---------------- gated = c[n] + d[idx] + nbr_fea @ W_edge + b ; BN1 stats ----------------
// 128 threads (one output column each), 8 atoms/block.
// Edge features transposed to f-major in smem so neighbor pairs pack into b64
// FFMA2 operands; W_edge column pre-duplicated into 41 packed registers.
__global__ void __launch_bounds__(128, 3)
gated_kernel(const float* __restrict__ nbr_fea, const int* __restrict__ nbr_idx,
             const float* __restrict__ W3, const float* __restrict__ bias)
{
    __shared__ __align__(16) float nf_t[NBRF * MM];  // [f][m], rows of 12 floats (48B, 16B-aligned)
    __shared__ int sidx[MM];
    const int o = threadIdx.x;

    ull w2[NBRF];
#pragma unroll
    for (int f = 0; f < NBRF; f++) w2[f] = dup2(W3[f * A2 + o]);
    const float b = bias[o];

    float s = 0.f, q = 0.f;
    const int atom0 = blockIdx.x * 8;

    for (int ai = 0; ai < 8; ai++) {
        const int n = atom0 + ai;
        // transpose 12x41 edge features into f-major smem
        for (int e = o; e < MM * NBRF; e += 128) {
            const int m = e / NBRF, f = e % NBRF;
            nf_t[f * MM + m] = nbr_fea[(size_t)n * (MM * NBRF) + e];
        }
        if (o < MM) sidx[o] = nbr_idx[n * MM + o];
        __syncthreads();

        float dm[MM];
#pragma unroll
        for (int m = 0; m < MM; m++) dm[m] = g_d[(size_t)sidx[m] * A2 + o];
        const float cb = g_c[(size_t)n * A2 + o] + b;

        ull y2[6];
#pragma unroll
        for (int mp = 0; mp < 6; mp++) y2[mp] = 0ULL;

#pragma unroll
        for (int f = 0; f < NBRF; f++) {
            const float* row = nf_t + f * MM;
            const ulonglong2 pa = *((const ulonglong2*)row);        // m0..m3
            const ulonglong2 pb = *((const ulonglong2*)(row + 4));  // m4..m7
            const ulonglong2 pc = *((const ulonglong2*)(row + 8));  // m8..m11
            fma2(y2[0], pa.x, w2[f]);
            fma2(y2[1], pa.y, w2[f]);
            fma2(y2[2], pb.x, w2[f]);
            fma2(y2[3], pb.y, w2[f]);
            fma2(y2[4], pc.x, w2[f]);
            fma2(y2[5], pc.y, w2[f]);
        }

        float* gout = g_gated + (size_t)n * (MM * A2) + o;
#pragma unroll
        for (int mp = 0; mp < 6; mp++) {
            const float2 e2 = unpack2(y2[mp]);
            const float y0 = e2.x + cb + dm[2 * mp];
            const float y1 = e2.y + cb + dm[2 * mp + 1];
            gout[(2 * mp) * A2]     = y0;
            gout[(2 * mp + 1) * A2] = y1;
            s += y0 + y1;
            q += y0 * y0 + y1 * y1;
        }
        __syncthreads();
    }
    atomicAdd(&g_s1[o], (double)s);
    atomicAdd(&g_q1[o], (double)q);
}

__global__ void finalize1_kernel(const float* __restrict__ g1, const float* __restrict__ b1) {
    const int o = threadIdx.x;
    const double cnt = (double)NN * MM;
    const double mean = g_s1[o] / cnt;
    const double var  = g_q1[o] / cnt - mean * mean;
    const float scale = g1[o] * rsqrtf((float)var + EPSL);
    g_scale1[o] = scale;
    g_shift1[o] = b1[o] - (float)mean * scale;
}

// ---------------- normalize, sigmoid*softplus, sum over M ; BN2 stats ----------------
__global__ void gatesum_kernel() {
    __shared__ float rs[4][64], rq[4][64];
    const int t = threadIdx.x;
    const int a = t % 64, set = t / 64;
    const float scf = g_scale1[a],      shf = g_shift1[a];
    const float scc = g_scale1[64 + a], shc = g_shift1[64 + a];

    float s = 0.f, q = 0.f;
    const int base_atom = blockIdx.x * 64 + set * 16;
    for (int i = 0; i < 16; i++) {
        const int n = base_atom + i;
        if (n >= NN) break;
        float acc = 0.f;
#pragma unroll 4
        for (int m = 0; m < MM; m++) {
            const size_t gb = ((size_t)n * MM + m) * A2;
            const float yf = g_gated[gb + a]      * scf + shf;
            const float yc = g_gated[gb + 64 + a] * scc + shc;
            acc += sg_f(yf) * sp_f(yc);
        }
        g_ns[n * 64 + a] = acc;
        s += acc; q += acc * acc;
    }
    rs[set][a] = s; rq[set][a] = q;
    __syncthreads();
    if (set == 0) {
        const float ts = rs[0][a] + rs[1][a] + rs[2][a] + rs[3][a];
        const float tq = rq[0][a] + rq[1][a] + rq[2][a] + rq[3][a];
        atomicAdd(&g_s2[a], (double)ts);
        atomicAdd(&g_q2[a], (double)tq);
    }
}

__global__ void finalize2_kernel(const float* __restrict__ g2, const float* __restrict__ b2) {
    const int a = threadIdx.x;
    const double cnt = (double)NN;
    const double mean = g_s2[a] / cnt;
    const double var  = g_q2[a] / cnt - mean * mean;
    const float scale = g2[a] * rsqrtf((float)var + EPSL);
    g_scale2[a] = scale;
    g_shift2[a] = b2[a] - (float)mean * scale;
}

__global__ void update_kernel() {
    const int i = blockIdx.x * blockDim.x + threadIdx.x;
    if (i >= NN * AA) return;
    const int a = i & 63;
    const float v = g_x[i] + g_ns[i] * g_scale2[a] + g_shift2[a];
    g_x[i] = sp_f(v);
}

// ---------------- pooling + head ----------------
__global__ void zero_pool_kernel() {
    const int i = blockIdx.x * blockDim.x + threadIdx.x;
    if (i < NC0 * AA) g_crys[i] = 0.f;
    if (i < NC0)      g_cnt[i]  = 0;
}

__global__ void pool_kernel(const int* __restrict__ cidx) {
    const int i = blockIdx.x * blockDim.x + threadIdx.x;
    if (i >= NN * AA) return;
    const int n = i >> 6, a = i & 63;
    const int c = cidx[n];
    atomicAdd(&g_crys[c * 64 + a], g_x[i]);
    if (a == 0) atomicAdd(&g_cnt[c], 1);
}

__global__ void head_kernel(const float* __restrict__ fc_W, const float* __restrict__ fc_b,
                            const float* __restrict__ out_W, const float* __restrict__ out_b,
                            float* __restrict__ out)
{
    __shared__ float spm[64];
    __shared__ float red[128];
    const int c = blockIdx.x, t = threadIdx.x;
    if (t < 64) {
        const float m = g_crys[c * 64 + t] / (float)g_cnt[c];
        spm[t] = sp_f(m);
    }
    __syncthreads();
    float h = fc_b[t];
#pragma unroll
    for (int a = 0; a < 64; a++) h += spm[a] * fc_W[a * HH + t];
    red[t] = sp_f(h) * out_W[t];
    __syncthreads();
    for (int sft = 64; sft > 0; sft >>= 1) {
        if (t < sft) red[t] += red[t + sft];
        __syncthreads();
    }
    if (t == 0) out[c] = red[0] + out_b[0];
}

// ---------------- host orchestration ----------------
extern "C" void kernel_launch(void* const* d_in, const int* in_sizes, int n_in,
                              void* d_out, int out_size)
{
    const float* atom_fea = (const float*)d_in[0];
    const float* nbr_fea  = (const float*)d_in[1];
    const int*   nbr_idx  = (const int*)  d_in[2];
    const int*   cidx     = (const int*)  d_in[3];
    const float* emb_W    = (const float*)d_in[4];
    const float* emb_b    = (const float*)d_in[5];
    const float* conv_W   = (const float*)d_in[6];
    const float* conv_b   = (const float*)d_in[7];
    const float* bn1_g    = (const float*)d_in[8];
    const float* bn1_b    = (const float*)d_in[9];
    const float* bn2_g    = (const float*)d_in[10];
    const float* bn2_b    = (const float*)d_in[11];
    const float* fc_W     = (const float*)d_in[12];
    const float* fc_b     = (const float*)d_in[13];
    const float* out_W    = (const float*)d_in[14];
    const float* out_b    = (const float*)d_in[15];
    float* out = (float*)d_out;

    float *px, *pc, *pd;
    cudaGetSymbolAddress((void**)&px, g_x);
    cudaGetSymbolAddress((void**)&pc, g_c);
    cudaGetSymbolAddress((void**)&pd, g_d);

    const int gemmBlocks = (NN + 63) / 64;

    gemm2_kernel<ORIGF, AA><<<gemmBlocks, 128>>>(atom_fea, emb_W, emb_b, px, NN);

    for (int i = 0; i < NCONVL; i++) {
        const float* Wl = conv_W + (size_t)i * (2 * AA + NBRF) * A2;
        zero_stats_kernel<<<1, 128>>>();
        gemm2_kernel<AA, A2><<<gemmBlocks, 128>>>(px, Wl,           nullptr, pc, NN);
        gemm2_kernel<AA, A2><<<gemmBlocks, 128>>>(px, Wl + 64 * A2, nullptr, pd, NN);
        gated_kernel<<<NN / 8, 128>>>(nbr_fea, nbr_idx, Wl + 128 * A2, conv_b + i * A2);
        finalize1_kernel<<<1, A2>>>(bn1_g + i * A2, bn1_b + i * A2);
        gatesum_kernel<<<(NN + 63) / 64, 256>>>();
        finalize2_kernel<<<1, AA>>>(bn2_g + i * AA, bn2_b + i * AA);
        update_kernel<<<(NN * AA + 255) / 256, 256>>>();
    }

    zero_pool_kernel<<<(NC0 * AA + 255) / 256, 256>>>();
    pool_kernel<<<(NN * AA + 255) / 256, 256>>>(cidx);
    head_kernel<<<NC0, 128>>>(fc_W, fc_b, out_W, out_b, out);
}

// round 3
// speedup vs baseline: 1.3901x; 1.1174x over previous
#include <cuda_runtime.h>
#include <cuda_fp16.h>
#include <math.h>

#define NN   100000
#define MM   12
#define ORIGF 92
#define NBRF 41
#define AA   64
#define A2   128
#define HH   128
#define NCONVL 3
#define NC0  1000
#define EPSL 1e-5f

typedef unsigned long long ull;

// ---------------- scratch (device globals; no runtime allocation) ----------------
__device__ float   g_x[NN * AA];
__device__ float   g_c[NN * A2];
__device__ float   g_d[NN * A2];
__device__ __half2 g_gatedh[(size_t)NN * 6 * A2];   // [n][m-pair][o], half2 over (2mp,2mp+1)
__device__ float   g_ns[NN * AA];
__device__ double  g_s1[A2], g_q1[A2];
__device__ double  g_s2[AA], g_q2[AA];
__device__ float   g_scale1[A2], g_shift1[A2];
__device__ float   g_scale2[AA], g_shift2[AA];
__device__ float   g_crys[NC0 * AA];
__device__ int     g_cnt[NC0];

// ---------------- f32x2 packed helpers ----------------
__device__ __forceinline__ ull pack2(float lo, float hi) {
    ull r; asm("mov.b64 %0, {%1, %2};" : "=l"(r) : "f"(lo), "f"(hi)); return r;
}
__device__ __forceinline__ ull dup2(float v) { return pack2(v, v); }
__device__ __forceinline__ void fma2(ull& d, ull a, ull b) {
    asm("fma.rn.f32x2 %0, %1, %2, %0;" : "+l"(d) : "l"(a), "l"(b));
}
__device__ __forceinline__ float2 unpack2(ull v) {
    float2 f; asm("mov.b64 {%0, %1}, %2;" : "=f"(f.x), "=f"(f.y) : "l"(v)); return f;
}

// ---------------- activations ----------------
__device__ __forceinline__ float sp_f(float x) {
    return fmaxf(x, 0.f) + __logf(1.f + __expf(-fabsf(x)));
}
__device__ __forceinline__ float sg_f(float x) {
    return __fdividef(1.f, 1.f + __expf(-x));
}

// ---------------- small GEMM, packed-K FFMA2, 256 threads ----------------
// out[N,O] = in[N,K] @ W[K,O] + b.  64 rows per block, 256/O row-groups.
template <int K, int O>
__global__ void gemm2_kernel(const float* __restrict__ in, const float* __restrict__ W,
                             const float* __restrict__ bias, float* __restrict__ out,
                             int nrows)
{
    __shared__ __align__(16) float sx[64 * K];
    const int t = threadIdx.x;
    const int o = t % O;
    const int grp = t / O;                 // 256/O groups
    const int rpt = 64 / (256 / O);        // rows per thread

    ull w2[K / 2];
#pragma unroll
    for (int k2 = 0; k2 < K / 2; k2++)
        w2[k2] = pack2(W[(2 * k2) * O + o], W[(2 * k2 + 1) * O + o]);
    const float bb = bias ? bias[o] : 0.f;

    const int row0 = blockIdx.x * 64;
    const int total4 = 64 * K / 4;
    for (int e = t; e < total4; e += 256) {
        const int r  = e / (K / 4);
        const int k4 = e % (K / 4);
        float4 v = make_float4(0.f, 0.f, 0.f, 0.f);
        const int rg = row0 + r;
        if (rg < nrows) v = *(((const float4*)(in + (size_t)rg * K)) + k4);
        *(((float4*)(sx + r * K)) + k4) = v;
    }
    __syncthreads();

#pragma unroll 4
    for (int rr = 0; rr < rpt; rr++) {
        const int r  = grp * rpt + rr;
        const int rg = row0 + r;
        ull c0 = 0ULL, c1 = 0ULL;
#pragma unroll
        for (int k4 = 0; k4 < K / 4; k4++) {
            const ulonglong2 p = *(((const ulonglong2*)(sx + r * K)) + k4);
            fma2(c0, p.x, w2[2 * k4]);
            fma2(c1, p.y, w2[2 * k4 + 1]);
        }
        if (rg < nrows) {
            const float2 f0 = unpack2(c0), f1 = unpack2(c1);
            out[(size_t)rg * O + o] = (f0.x + f0.y) + (f1.x + f1.y) + bb;
        }
    }
}

// ---------------- zero BN stats ----------------
__global__ void zero_stats_kernel() {
    const int t = threadIdx.x;
    if (t < A2) { g_s1[t] = 0.0; g_q1[t] = 0.0; }
    if (t < AA) { g_s2[t] = 0.0; g_q2[t] = 0.0; }
}

// ---------------- gated = c[n] + d[idx] + nbr_fea @ W_edge + b ; BN1 stats ----------------
// 128 threads (one output column each), 8 atoms/block, double-buffered smem prefetch.
__global__ void __launch_bounds__(128, 4)
gated_kernel(const float* __restrict__ nbr_fea, const int* __restrict__ nbr_idx,
             const float* __restrict__ W3, const float* __restrict__ bias)
{
    __shared__ __align__(16) float nf_t[2][NBRF * MM];  // [buf][f][m]
    __shared__ int sidx[2][MM];
    const int o = threadIdx.x;

    ull w2[NBRF];
#pragma unroll
    for (int f = 0; f < NBRF; f++) w2[f] = dup2(W3[f * A2 + o]);
    const float b = bias[o];

    const int atom0 = blockIdx.x * 8;

    // prologue: stage atom0 into buffer 0
    {
        const size_t base = (size_t)atom0 * (MM * NBRF);
        for (int e = o; e < MM * NBRF; e += 128) {
            const int m = e / NBRF, f = e % NBRF;
            nf_t[0][f * MM + m] = nbr_fea[base + e];
        }
        if (o < MM) sidx[0][o] = nbr_idx[atom0 * MM + o];
    }
    __syncthreads();

    float s = 0.f, q = 0.f;

    for (int ai = 0; ai < 8; ai++) {
        const int cur = ai & 1, nxt = cur ^ 1;
        const int n = atom0 + ai;

        // gather d rows for current atom (consumed only in epilogue -> latency hidden)
        float dm[MM];
#pragma unroll
        for (int m = 0; m < MM; m++) dm[m] = g_d[(size_t)sidx[cur][m] * A2 + o];
        const float cb = g_c[(size_t)n * A2 + o] + b;

        // prefetch next atom's edge tile + indices into the other buffer
        if (ai < 7) {
            const int n2 = n + 1;
            const size_t base = (size_t)n2 * (MM * NBRF);
            for (int e = o; e < MM * NBRF; e += 128) {
                const int m = e / NBRF, f = e % NBRF;
                nf_t[nxt][f * MM + m] = nbr_fea[base + e];
            }
            if (o < MM) sidx[nxt][o] = nbr_idx[n2 * MM + o];
        }

        // edge GEMM: packed over neighbor pairs
        ull y2[6];
#pragma unroll
        for (int mp = 0; mp < 6; mp++) y2[mp] = 0ULL;
#pragma unroll
        for (int f = 0; f < NBRF; f++) {
            const float* row = nf_t[cur] + f * MM;
            const ulonglong2 pa = *((const ulonglong2*)row);
            const ulonglong2 pb = *((const ulonglong2*)(row + 4));
            const ulonglong2 pc = *((const ulonglong2*)(row + 8));
            fma2(y2[0], pa.x, w2[f]);
            fma2(y2[1], pa.y, w2[f]);
            fma2(y2[2], pb.x, w2[f]);
            fma2(y2[3], pb.y, w2[f]);
            fma2(y2[4], pc.x, w2[f]);
            fma2(y2[5], pc.y, w2[f]);
        }

        // epilogue: add central + neighbor terms, store half2, accumulate stats
        __half2* gout = g_gatedh + (size_t)n * (6 * A2) + o;
#pragma unroll
        for (int mp = 0; mp < 6; mp++) {
            const float2 e2 = unpack2(y2[mp]);
            const float y0 = e2.x + cb + dm[2 * mp];
            const float y1 = e2.y + cb + dm[2 * mp + 1];
            gout[mp * A2] = __floats2half2_rn(y0, y1);
            s += y0 + y1;
            q += y0 * y0 + y1 * y1;
        }
        __syncthreads();
    }
    atomicAdd(&g_s1[o], (double)s);
    atomicAdd(&g_q1[o], (double)q);
}

__global__ void finalize1_kernel(const float* __restrict__ g1, const float* __restrict__ b1) {
    const int o = threadIdx.x;
    const double cnt = (double)NN * MM;
    const double mean = g_s1[o] / cnt;
    const double var  = g_q1[o] / cnt - mean * mean;
    const float scale = g1[o] * rsqrtf((float)var + EPSL);
    g_scale1[o] = scale;
    g_shift1[o] = b1[o] - (float)mean * scale;
}

// ---------------- normalize, sigmoid*softplus, sum over M ; BN2 stats ----------------
__global__ void gatesum_kernel() {
    __shared__ float rs[4][64], rq[4][64];
    const int t = threadIdx.x;
    const int a = t % 64, set = t / 64;
    const float scf = g_scale1[a],      shf = g_shift1[a];
    const float scc = g_scale1[64 + a], shc = g_shift1[64 + a];

    float s = 0.f, q = 0.f;
    const int base_atom = blockIdx.x * 64 + set * 16;
    for (int i = 0; i < 16; i++) {
        const int n = base_atom + i;
        if (n >= NN) break;
        const __half2* gin = g_gatedh + (size_t)n * (6 * A2);
        float acc = 0.f;
#pragma unroll
        for (int mp = 0; mp < 6; mp++) {
            const float2 f2 = __half22float2(gin[mp * A2 + a]);
            const float2 c2 = __half22float2(gin[mp * A2 + 64 + a]);
            const float yf0 = f2.x * scf + shf, yf1 = f2.y * scf + shf;
            const float yc0 = c2.x * scc + shc, yc1 = c2.y * scc + shc;
            acc += sg_f(yf0) * sp_f(yc0) + sg_f(yf1) * sp_f(yc1);
        }
        g_ns[n * 64 + a] = acc;
        s += acc; q += acc * acc;
    }
    rs[set][a] = s; rq[set][a] = q;
    __syncthreads();
    if (set == 0) {
        const float ts = rs[0][a] + rs[1][a] + rs[2][a] + rs[3][a];
        const float tq = rq[0][a] + rq[1][a] + rq[2][a] + rq[3][a];
        atomicAdd(&g_s2[a], (double)ts);
        atomicAdd(&g_q2[a], (double)tq);
    }
}

__global__ void finalize2_kernel(const float* __restrict__ g2, const float* __restrict__ b2) {
    const int a = threadIdx.x;
    const double cnt = (double)NN;
    const double mean = g_s2[a] / cnt;
    const double var  = g_q2[a] / cnt - mean * mean;
    const float scale = g2[a] * rsqrtf((float)var + EPSL);
    g_scale2[a] = scale;
    g_shift2[a] = b2[a] - (float)mean * scale;
}

__global__ void update_kernel() {
    const int i = blockIdx.x * blockDim.x + threadIdx.x;
    if (i >= NN * AA) return;
    const int a = i & 63;
    const float v = g_x[i] + g_ns[i] * g_scale2[a] + g_shift2[a];
    g_x[i] = sp_f(v);
}

// ---------------- pooling + head ----------------
__global__ void zero_pool_kernel() {
    const int i = blockIdx.x * blockDim.x + threadIdx.x;
    if (i < NC0 * AA) g_crys[i] = 0.f;
    if (i < NC0)      g_cnt[i]  = 0;
}

__global__ void pool_kernel(const int* __restrict__ cidx) {
    const int i = blockIdx.x * blockDim.x + threadIdx.x;
    if (i >= NN * AA) return;
    const int n = i >> 6, a = i & 63;
    const int c = cidx[n];
    atomicAdd(&g_crys[c * 64 + a], g_x[i]);
    if (a == 0) atomicAdd(&g_cnt[c], 1);
}

__global__ void head_kernel(const float* __restrict__ fc_W, const float* __restrict__ fc_b,
                            const float* __restrict__ out_W, const float* __restrict__ out_b,
                            float* __restrict__ out)
{
    __shared__ float spm[64];
    __shared__ float red[128];
    const int c = blockIdx.x, t = threadIdx.x;
    if (t < 64) {
        const float m = g_crys[c * 64 + t] / (float)g_cnt[c];
        spm[t] = sp_f(m);
    }
    __syncthreads();
    float h = fc_b[t];
#pragma unroll
    for (int a = 0; a < 64; a++) h += spm[a] * fc_W[a * HH + t];
    red[t] = sp_f(h) * out_W[t];
    __syncthreads();
    for (int sft = 64; sft > 0; sft >>= 1) {
        if (t < sft) red[t] += red[t + sft];
        __syncthreads();
    }
    if (t == 0) out[c] = red[0] + out_b[0];
}

// ---------------- host orchestration ----------------
extern "C" void kernel_launch(void* const* d_in, const int* in_sizes, int n_in,
                              void* d_out, int out_size)
{
    const float* atom_fea = (const float*)d_in[0];
    const float* nbr_fea  = (const float*)d_in[1];
    const int*   nbr_idx  = (const int*)  d_in[2];
    const int*   cidx     = (const int*)  d_in[3];
    const float* emb_W    = (const float*)d_in[4];
    const float* emb_b    = (const float*)d_in[5];
    const float* conv_W   = (const float*)d_in[6];
    const float* conv_b   = (const float*)d_in[7];
    const float* bn1_g    = (const float*)d_in[8];
    const float* bn1_b    = (const float*)d_in[9];
    const float* bn2_g    = (const float*)d_in[10];
    const float* bn2_b    = (const float*)d_in[11];
    const float* fc_W     = (const float*)d_in[12];
    const float* fc_b     = (const float*)d_in[13];
    const float* out_W    = (const float*)d_in[14];
    const float* out_b    = (const float*)d_in[15];
    float* out = (float*)d_out;

    float *px, *pc, *pd;
    cudaGetSymbolAddress((void**)&px, g_x);
    cudaGetSymbolAddress((void**)&pc, g_c);
    cudaGetSymbolAddress((void**)&pd, g_d);

    const int gemmBlocks = (NN + 63) / 64;

    gemm2_kernel<ORIGF, AA><<<gemmBlocks, 256>>>(atom_fea, emb_W, emb_b, px, NN);

    for (int i = 0; i < NCONVL; i++) {
        const float* Wl = conv_W + (size_t)i * (2 * AA + NBRF) * A2;
        zero_stats_kernel<<<1, 128>>>();
        gemm2_kernel<AA, A2><<<gemmBlocks, 256>>>(px, Wl,           nullptr, pc, NN);
        gemm2_kernel<AA, A2><<<gemmBlocks, 256>>>(px, Wl + 64 * A2, nullptr, pd, NN);
        gated_kernel<<<NN / 8, 128>>>(nbr_fea, nbr_idx, Wl + 128 * A2, conv_b + i * A2);
        finalize1_kernel<<<1, A2>>>(bn1_g + i * A2, bn1_b + i * A2);
        gatesum_kernel<<<(NN + 63) / 64, 256>>>();
        finalize2_kernel<<<1, AA>>>(bn2_g + i * AA, bn2_b + i * AA);
        update_kernel<<<(NN * AA + 255) / 256, 256>>>();
    }

    zero_pool_kernel<<<(NC0 * AA + 255) / 256, 256>>>();
    pool_kernel<<<(NN * AA + 255) / 256, 256>>>(cidx);
    head_kernel<<<NC0, 128>>>(fc_W, fc_b, out_W, out_b, out);
}

// round 5
// speedup vs baseline: 1.4655x; 1.0543x over previous
#include <cuda_runtime.h>
#include <cuda_fp16.h>
#include <math.h>

#define NN   100000
#define MM   12
#define ORIGF 92
#define NBRF 41
#define AA   64
#define A2   128
#define HH   128
#define NCONVL 3
#define NC0  1000
#define EPSL 1e-5f

typedef unsigned long long ull;

// ---------------- scratch ----------------
__device__ float   g_x[NN * AA];
__device__ float   g_c[NN * A2];
__device__ float   g_d[NN * A2];
__device__ __half2 g_gatedh[(size_t)NN * 6 * A2];   // [n][m-pair][o]
__device__ float   g_ns[NN * AA];
__device__ double  g_s1[A2], g_q1[A2];
__device__ double  g_s2[AA], g_q2[AA];
__device__ float   g_scale1[A2], g_shift1[A2];
__device__ float   g_scale2[AA], g_shift2[AA];

// ---------------- f32x2 helpers ----------------
__device__ __forceinline__ ull pack2(float lo, float hi) {
    ull r; asm("mov.b64 %0, {%1, %2};" : "=l"(r) : "f"(lo), "f"(hi)); return r;
}
__device__ __forceinline__ ull dup2(float v) { return pack2(v, v); }
__device__ __forceinline__ void fma2(ull& d, ull a, ull b) {
    asm("fma.rn.f32x2 %0, %1, %2, %0;" : "+l"(d) : "l"(a), "l"(b));
}
__device__ __forceinline__ float2 unpack2(ull v) {
    float2 f; asm("mov.b64 {%0, %1}, %2;" : "=f"(f.x), "=f"(f.y) : "l"(v)); return f;
}

// ---------------- activations ----------------
__device__ __forceinline__ float sp_f(float x) {
    return fmaxf(x, 0.f) + __logf(1.f + __expf(-fabsf(x)));
}
__device__ __forceinline__ float sg_f(float x) {
    return __fdividef(1.f, 1.f + __expf(-x));
}

// ================= tiled GEMM: out[N,O] = in[N,K] @ W[K,O] + b =================
// 64 rows x O cols per block. Threads = 16 rowgrps x (O/8) colgrps.
// A transposed [K][64] raw floats (dup to b64 in regs); W raw [K][O]
// (adjacent col-pairs pack into FFMA2 operands for free).
// smem: K*64*4 + K*O*4 bytes  (<= 48KB for both instantiations -> no attribute call)
template <int K, int O>
__global__ void __launch_bounds__(256)
gemmT_kernel(const float* __restrict__ in, const float* __restrict__ W,
             const float* __restrict__ bias, float* __restrict__ out, int nrows)
{
    extern __shared__ char dsm[];
    float* saT = (float*)dsm;                          // [K][64] transposed A
    float* sW  = (float*)(dsm + (size_t)K * 64 * 4);   // [K][O]

    const int nt = blockDim.x;
    const int t  = threadIdx.x;
    const int CG = O / 8;
    const int rg = t / CG;          // 0..15
    const int cg = t % CG;
    const int r0 = rg * 4;
    const int c0 = cg * 8;
    const int row0 = blockIdx.x * 64;

    // fill A (transposed)
    for (int idx = t; idx < 64 * (K / 4); idx += nt) {
        const int r  = idx / (K / 4);
        const int kq = idx % (K / 4);
        float4 v = make_float4(0.f, 0.f, 0.f, 0.f);
        if (row0 + r < nrows) v = *(((const float4*)(in + (size_t)(row0 + r) * K)) + kq);
        saT[(4 * kq + 0) * 64 + r] = v.x;
        saT[(4 * kq + 1) * 64 + r] = v.y;
        saT[(4 * kq + 2) * 64 + r] = v.z;
        saT[(4 * kq + 3) * 64 + r] = v.w;
    }
    // fill W (direct coalesced copy, row-major [K][O])
    for (int idx = t; idx < K * O / 4; idx += nt)
        ((float4*)sW)[idx] = ((const float4*)W)[idx];
    __syncthreads();

    ull acc[4][4];
#pragma unroll
    for (int r = 0; r < 4; r++)
#pragma unroll
        for (int cp = 0; cp < 4; cp++) acc[r][cp] = 0ULL;

    for (int k = 0; k < K; k++) {
        const float4 av = *((const float4*)(saT + k * 64 + r0));
        const ull A0 = dup2(av.x), A1 = dup2(av.y), A2r = dup2(av.z), A3 = dup2(av.w);
        const float* wr = sW + k * O + c0;
        const ulonglong2 W03 = *((const ulonglong2*)wr);
        const ulonglong2 W47 = *((const ulonglong2*)(wr + 4));
        fma2(acc[0][0], A0, W03.x);  fma2(acc[0][1], A0, W03.y);
        fma2(acc[0][2], A0, W47.x);  fma2(acc[0][3], A0, W47.y);
        fma2(acc[1][0], A1, W03.x);  fma2(acc[1][1], A1, W03.y);
        fma2(acc[1][2], A1, W47.x);  fma2(acc[1][3], A1, W47.y);
        fma2(acc[2][0], A2r, W03.x); fma2(acc[2][1], A2r, W03.y);
        fma2(acc[2][2], A2r, W47.x); fma2(acc[2][3], A2r, W47.y);
        fma2(acc[3][0], A3, W03.x);  fma2(acc[3][1], A3, W03.y);
        fma2(acc[3][2], A3, W47.x);  fma2(acc[3][3], A3, W47.y);
    }

    float bb[8];
#pragma unroll
    for (int c = 0; c < 8; c++) bb[c] = bias ? bias[c0 + c] : 0.f;

#pragma unroll
    for (int r = 0; r < 4; r++) {
        const int rgl = row0 + r0 + r;
        if (rgl >= nrows) continue;
        float y[8];
#pragma unroll
        for (int cp = 0; cp < 4; cp++) {
            const float2 f = unpack2(acc[r][cp]);
            y[2 * cp]     = f.x + bb[2 * cp];
            y[2 * cp + 1] = f.y + bb[2 * cp + 1];
        }
        float4* op = (float4*)(out + (size_t)rgl * O + c0);
        op[0] = make_float4(y[0], y[1], y[2], y[3]);
        op[1] = make_float4(y[4], y[5], y[6], y[7]);
    }
}

// ---------------- zero BN stats ----------------
__global__ void zero_stats_kernel() {
    const int t = threadIdx.x;
    if (t < A2) { g_s1[t] = 0.0; g_q1[t] = 0.0; }
    if (t < AA) { g_s2[t] = 0.0; g_q2[t] = 0.0; }
}

// ================= gated: per-warp 12x128 edge GEMM + assemble =================
// 128 threads = 4 atom-slots (warps) x 32 col-groups (4 cols each).
// 16 atoms per block in 4 double-buffered batches.
__global__ void __launch_bounds__(128, 3)
gated_kernel(const float* __restrict__ nbr_fea, const int* __restrict__ nbr_idx,
             const float* __restrict__ W3, const float* __restrict__ bias)
{
    __shared__ __align__(16) float sW3[NBRF * A2];          // [f][o] raw
    __shared__ __align__(16) float s_nf[2][4][NBRF * MM];   // [buf][slot][f*12+m]
    __shared__ int s_idx[2][4][MM];

    const int t    = threadIdx.x;
    const int slot = t >> 5;           // warp = atom slot
    const int u    = t & 31;           // col group: cols 4u..4u+3
    const int col0 = 4 * u;
    const int atom0 = blockIdx.x * 16;

    // W3 to smem (coalesced copy)
    for (int i = t; i < NBRF * A2; i += 128) sW3[i] = W3[i];

    // prologue: stage batch 0
    for (int e = t; e < 4 * MM * NBRF; e += 128) {
        const int sl = e / (MM * NBRF), rem = e % (MM * NBRF);
        const int m = rem / NBRF, f = rem % NBRF;
        s_nf[0][sl][f * MM + m] = nbr_fea[(size_t)(atom0 + sl) * (MM * NBRF) + rem];
    }
    if (t < 4 * MM) s_idx[0][t / MM][t % MM] = nbr_idx[(atom0 + t / MM) * MM + t % MM];

    const float4 bvec = *((const float4*)(bias + col0));
    float sc[4] = {0.f, 0.f, 0.f, 0.f}, qc[4] = {0.f, 0.f, 0.f, 0.f};
    __syncthreads();

    for (int b = 0; b < 4; b++) {
        const int cur = b & 1, nxt = cur ^ 1;
        const int n = atom0 + b * 4 + slot;

        // issue gathers early (consumed only in epilogue -> latency hidden)
        float4 dm[MM];
#pragma unroll
        for (int m = 0; m < MM; m++)
            dm[m] = *((const float4*)(g_d + (size_t)s_idx[cur][slot][m] * A2 + col0));
        const float4 cv = *((const float4*)(g_c + (size_t)n * A2 + col0));
        float cb[4] = {cv.x + bvec.x, cv.y + bvec.y, cv.z + bvec.z, cv.w + bvec.w};

        // prefetch next batch
        if (b < 3) {
            const int na0 = atom0 + (b + 1) * 4;
            for (int e = t; e < 4 * MM * NBRF; e += 128) {
                const int sl = e / (MM * NBRF), rem = e % (MM * NBRF);
                const int m = rem / NBRF, f = rem % NBRF;
                s_nf[nxt][sl][f * MM + m] = nbr_fea[(size_t)(na0 + sl) * (MM * NBRF) + rem];
            }
            if (t < 4 * MM) s_idx[nxt][t / MM][t % MM] = nbr_idx[(na0 + t / MM) * MM + t % MM];
        }

        // 12x4 edge GEMM over f (24 independent FFMA2 chains)
        ull acc[6][4];
#pragma unroll
        for (int mp = 0; mp < 6; mp++)
#pragma unroll
            for (int c = 0; c < 4; c++) acc[mp][c] = 0ULL;

        const float* nfb = s_nf[cur][slot];
#pragma unroll 1
        for (int f = 0; f < NBRF; f++) {
            const float4 w4 = *((const float4*)(sW3 + f * A2 + col0));
            const ull wd0 = dup2(w4.x), wd1 = dup2(w4.y), wd2 = dup2(w4.z), wd3 = dup2(w4.w);
            const float* row = nfb + f * MM;
            const ulonglong2 pa = *((const ulonglong2*)row);
            const ulonglong2 pb = *((const ulonglong2*)(row + 4));
            const ulonglong2 pc = *((const ulonglong2*)(row + 8));
            fma2(acc[0][0], pa.x, wd0); fma2(acc[0][1], pa.x, wd1);
            fma2(acc[0][2], pa.x, wd2); fma2(acc[0][3], pa.x, wd3);
            fma2(acc[1][0], pa.y, wd0); fma2(acc[1][1], pa.y, wd1);
            fma2(acc[1][2], pa.y, wd2); fma2(acc[1][3], pa.y, wd3);
            fma2(acc[2][0], pb.x, wd0); fma2(acc[2][1], pb.x, wd1);
            fma2(acc[2][2], pb.x, wd2); fma2(acc[2][3], pb.x, wd3);
            fma2(acc[3][0], pb.y, wd0); fma2(acc[3][1], pb.y, wd1);
            fma2(acc[3][2], pb.y, wd2); fma2(acc[3][3], pb.y, wd3);
            fma2(acc[4][0], pc.x, wd0); fma2(acc[4][1], pc.x, wd1);
            fma2(acc[4][2], pc.x, wd2); fma2(acc[4][3], pc.x, wd3);
            fma2(acc[5][0], pc.y, wd0); fma2(acc[5][1], pc.y, wd1);
            fma2(acc[5][2], pc.y, wd2); fma2(acc[5][3], pc.y, wd3);
        }

        // epilogue: assemble, half2 store (coalesced 16B/thread), stats
        __half2* gout = g_gatedh + (size_t)n * (6 * A2) + col0;
#pragma unroll
        for (int mp = 0; mp < 6; mp++) {
            const float* d0 = (const float*)&dm[2 * mp];
            const float* d1 = (const float*)&dm[2 * mp + 1];
            uint4 st;
            unsigned* stv = (unsigned*)&st;
#pragma unroll
            for (int c = 0; c < 4; c++) {
                const float2 e2 = unpack2(acc[mp][c]);
                const float y0 = e2.x + cb[c] + d0[c];
                const float y1 = e2.y + cb[c] + d1[c];
                __half2 h = __floats2half2_rn(y0, y1);
                stv[c] = *(unsigned*)&h;
                sc[c] += y0 + y1;
                qc[c] += y0 * y0 + y1 * y1;
            }
            *((uint4*)(gout + mp * A2)) = st;
        }
        __syncthreads();
    }

    // per-column stats: reduce across the 4 atom-slots in smem, then atomics
    float* scr = (float*)&s_nf[0][0][0];   // reuse (needs 1024 floats, has 3936)
#pragma unroll
    for (int c = 0; c < 4; c++) {
        scr[slot * A2 + col0 + c]       = sc[c];
        scr[512 + slot * A2 + col0 + c] = qc[c];
    }
    __syncthreads();
    if (slot == 0) {
#pragma unroll
        for (int c = 0; c < 4; c++) {
            const int o = col0 + c;
            const float ts = scr[o] + scr[A2 + o] + scr[2 * A2 + o] + scr[3 * A2 + o];
            const float tq = scr[512 + o] + scr[512 + A2 + o] + scr[512 + 2 * A2 + o] + scr[512 + 3 * A2 + o];
            atomicAdd(&g_s1[o], (double)ts);
            atomicAdd(&g_q1[o], (double)tq);
        }
    }
}

__global__ void finalize1_kernel(const float* __restrict__ g1, const float* __restrict__ b1) {
    const int o = threadIdx.x;
    const double cnt = (double)NN * MM;
    const double mean = g_s1[o] / cnt;
    const double var  = g_q1[o] / cnt - mean * mean;
    const float scale = g1[o] * rsqrtf((float)var + EPSL);
    g_scale1[o] = scale;
    g_shift1[o] = b1[o] - (float)mean * scale;
}

// ---------------- normalize, sigmoid*softplus, sum over M ; BN2 stats ----------------
__global__ void gatesum_kernel() {
    __shared__ float rs[4][64], rq[4][64];
    const int t = threadIdx.x;
    const int a = t % 64, set = t / 64;
    const float scf = g_scale1[a],      shf = g_shift1[a];
    const float scc = g_scale1[64 + a], shc = g_shift1[64 + a];

    float s = 0.f, q = 0.f;
    const int base_atom = blockIdx.x * 64 + set * 16;
    for (int i = 0; i < 16; i++) {
        const int n = base_atom + i;
        if (n >= NN) break;
        const __half2* gin = g_gatedh + (size_t)n * (6 * A2);
        float acc = 0.f;
#pragma unroll
        for (int mp = 0; mp < 6; mp++) {
            const float2 f2 = __half22float2(gin[mp * A2 + a]);
            const float2 c2 = __half22float2(gin[mp * A2 + 64 + a]);
            const float yf0 = f2.x * scf + shf, yf1 = f2.y * scf + shf;
            const float yc0 = c2.x * scc + shc, yc1 = c2.y * scc + shc;
            acc += sg_f(yf0) * sp_f(yc0) + sg_f(yf1) * sp_f(yc1);
        }
        g_ns[n * 64 + a] = acc;
        s += acc; q += acc * acc;
    }
    rs[set][a] = s; rq[set][a] = q;
    __syncthreads();
    if (set == 0) {
        atomicAdd(&g_s2[a], (double)(rs[0][a] + rs[1][a] + rs[2][a] + rs[3][a]));
        atomicAdd(&g_q2[a], (double)(rq[0][a] + rq[1][a] + rq[2][a] + rq[3][a]));
    }
}

__global__ void finalize2_kernel(const float* __restrict__ g2, const float* __restrict__ b2) {
    const int a = threadIdx.x;
    const double cnt = (double)NN;
    const double mean = g_s2[a] / cnt;
    const double var  = g_q2[a] / cnt - mean * mean;
    const float scale = g2[a] * rsqrtf((float)var + EPSL);
    g_scale2[a] = scale;
    g_shift2[a] = b2[a] - (float)mean * scale;
}

__global__ void update_kernel() {
    const int i = blockIdx.x * blockDim.x + threadIdx.x;
    if (i >= NN * AA) return;
    const int a = i & 63;
    const float v = g_x[i] + g_ns[i] * g_scale2[a] + g_shift2[a];
    g_x[i] = sp_f(v);
}

// ---------------- fused pool + head (crystals are 100 contiguous atoms) ----------------
__global__ void head2_kernel(const float* __restrict__ fc_W, const float* __restrict__ fc_b,
                             const float* __restrict__ out_W, const float* __restrict__ out_b,
                             float* __restrict__ out)
{
    __shared__ float sred[2][64];
    __shared__ float spm[64];
    __shared__ float red[128];
    const int c = blockIdx.x, t = threadIdx.x;
    const int a = t & 63, half = t >> 6;

    float s = 0.f;
    const int r0 = c * 100 + half * 50;
    for (int i = 0; i < 50; i++) s += g_x[(r0 + i) * 64 + a];
    sred[half][a] = s;
    __syncthreads();
    if (t < 64) spm[t] = sp_f((sred[0][t] + sred[1][t]) * 0.01f);
    __syncthreads();

    float h = fc_b[t];
#pragma unroll
    for (int aa = 0; aa < 64; aa++) h += spm[aa] * fc_W[aa * HH + t];
    red[t] = sp_f(h) * out_W[t];
    __syncthreads();
    for (int sft = 64; sft > 0; sft >>= 1) {
        if (t < sft) red[t] += red[t + sft];
        __syncthreads();
    }
    if (t == 0) out[c] = red[0] + out_b[0];
}

// ---------------- host orchestration ----------------
extern "C" void kernel_launch(void* const* d_in, const int* in_sizes, int n_in,
                              void* d_out, int out_size)
{
    const float* atom_fea = (const float*)d_in[0];
    const float* nbr_fea  = (const float*)d_in[1];
    const int*   nbr_idx  = (const int*)  d_in[2];
    const float* emb_W    = (const float*)d_in[4];
    const float* emb_b    = (const float*)d_in[5];
    const float* conv_W   = (const float*)d_in[6];
    const float* conv_b   = (const float*)d_in[7];
    const float* bn1_g    = (const float*)d_in[8];
    const float* bn1_b    = (const float*)d_in[9];
    const float* bn2_g    = (const float*)d_in[10];
    const float* bn2_b    = (const float*)d_in[11];
    const float* fc_W     = (const float*)d_in[12];
    const float* fc_b     = (const float*)d_in[13];
    const float* out_W    = (const float*)d_in[14];
    const float* out_b    = (const float*)d_in[15];
    float* out = (float*)d_out;

    float *px, *pc, *pd;
    cudaGetSymbolAddress((void**)&px, g_x);
    cudaGetSymbolAddress((void**)&pc, g_c);
    cudaGetSymbolAddress((void**)&pd, g_d);

    const size_t smemE = (size_t)ORIGF * 64 * 4 + (size_t)ORIGF * AA * 4;  // 46KB
    const size_t smemC = (size_t)AA * 64 * 4 + (size_t)AA * A2 * 4;        // 48KB exactly

    const int gemmBlocks = (NN + 63) / 64;

    gemmT_kernel<ORIGF, AA><<<gemmBlocks, 128, smemE>>>(atom_fea, emb_W, emb_b, px, NN);

    for (int i = 0; i < NCONVL; i++) {
        const float* Wl = conv_W + (size_t)i * (2 * AA + NBRF) * A2;
        zero_stats_kernel<<<1, 128>>>();
        gemmT_kernel<AA, A2><<<gemmBlocks, 256, smemC>>>(px, Wl,           nullptr, pc, NN);
        gemmT_kernel<AA, A2><<<gemmBlocks, 256, smemC>>>(px, Wl + 64 * A2, nullptr, pd, NN);
        gated_kernel<<<NN / 16, 128>>>(nbr_fea, nbr_idx, Wl + 128 * A2, conv_b + i * A2);
        finalize1_kernel<<<1, A2>>>(bn1_g + i * A2, bn1_b + i * A2);
        gatesum_kernel<<<(NN + 63) / 64, 256>>>();
        finalize2_kernel<<<1, AA>>>(bn2_g + i * AA, bn2_b + i * AA);
        update_kernel<<<(NN * AA + 255) / 256, 256>>>();
    }

    head2_kernel<<<NC0, 128>>>(fc_W, fc_b, out_W, out_b, out);
}

// round 7
// speedup vs baseline: 1.5306x; 1.0444x over previous
#include <cuda_runtime.h>
#include <cuda_fp16.h>
#include <math.h>

#define NN   100000
#define MM   12
#define ORIGF 92
#define NBRF 41
#define AA   64
#define A2   128
#define HH   128
#define NCONVL 3
#define NC0  1000
#define EPSL 1e-5f
#define NFE  (MM * NBRF)        // 492 edge features per atom

typedef unsigned long long ull;

// ---------------- scratch ----------------
__device__ float   g_x[NN * AA];
__device__ float   g_c[NN * A2];
__device__ float   g_d[NN * A2];
__device__ __half  g_nfh[(size_t)NN * NFE];         // nbr_fea transposed [n][f][m], fp16
__device__ __half2 g_gatedh[(size_t)NN * 6 * A2];   // [n][m-pair][o]
__device__ float   g_ns[NN * AA];
__device__ double  g_s1[A2], g_q1[A2];
__device__ double  g_s2[AA], g_q2[AA];
__device__ float   g_scale1[A2], g_shift1[A2];
__device__ float   g_scale2[AA], g_shift2[AA];

// ---------------- f32x2 helpers ----------------
__device__ __forceinline__ ull pack2(float lo, float hi) {
    ull r; asm("mov.b64 %0, {%1, %2};" : "=l"(r) : "f"(lo), "f"(hi)); return r;
}
__device__ __forceinline__ ull dup2(float v) { return pack2(v, v); }
__device__ __forceinline__ void fma2(ull& d, ull a, ull b) {
    asm("fma.rn.f32x2 %0, %1, %2, %0;" : "+l"(d) : "l"(a), "l"(b));
}
__device__ __forceinline__ float2 unpack2(ull v) {
    float2 f; asm("mov.b64 {%0, %1}, %2;" : "=f"(f.x), "=f"(f.y) : "l"(v)); return f;
}

// ---------------- activations ----------------
__device__ __forceinline__ float sp_f(float x) {
    return fmaxf(x, 0.f) + __logf(1.f + __expf(-fabsf(x)));
}
__device__ __forceinline__ float sg_f(float x) {
    return __fdividef(1.f, 1.f + __expf(-x));
}

// ================= nbr_fea -> transposed fp16, once =================
__global__ void nf2half_kernel(const float* __restrict__ nbr_fea) {
    __shared__ float s[8 * NFE];
    const int t = threadIdx.x;
    const int n0 = blockIdx.x * 8;
    if (n0 >= NN) return;
    for (int e = t; e < 8 * NFE; e += 128) {
        const int a = e / NFE;
        if (n0 + a < NN) s[e] = nbr_fea[(size_t)n0 * NFE + e];
    }
    __syncthreads();
    for (int e = t; e < 8 * NFE; e += 128) {
        const int a = e / NFE, r = e % NFE;
        if (n0 + a >= NN) continue;
        const int f = r / MM, m = r % MM;
        g_nfh[(size_t)(n0 + a) * NFE + r] = __float2half(s[a * NFE + m * NBRF + f]);
    }
}

// ================= embedding GEMM (once): out[N,64] = in[N,92] @ W + b ========
template <int K, int O>
__global__ void __launch_bounds__(256)
gemmT_kernel(const float* __restrict__ in, const float* __restrict__ W,
             const float* __restrict__ bias, float* __restrict__ out, int nrows)
{
    extern __shared__ char dsm[];
    float* saT = (float*)dsm;                          // [K][64]
    float* sW  = (float*)(dsm + (size_t)K * 64 * 4);   // [K][O]

    const int nt = blockDim.x;
    const int t  = threadIdx.x;
    const int CG = O / 8;
    const int rg = t / CG;
    const int cg = t % CG;
    const int r0 = rg * 4;
    const int c0 = cg * 8;
    const int row0 = blockIdx.x * 64;

    for (int idx = t; idx < 64 * (K / 4); idx += nt) {
        const int r  = idx / (K / 4);
        const int kq = idx % (K / 4);
        float4 v = make_float4(0.f, 0.f, 0.f, 0.f);
        if (row0 + r < nrows) v = *(((const float4*)(in + (size_t)(row0 + r) * K)) + kq);
        saT[(4 * kq + 0) * 64 + r] = v.x;
        saT[(4 * kq + 1) * 64 + r] = v.y;
        saT[(4 * kq + 2) * 64 + r] = v.z;
        saT[(4 * kq + 3) * 64 + r] = v.w;
    }
    for (int idx = t; idx < K * O / 4; idx += nt)
        ((float4*)sW)[idx] = ((const float4*)W)[idx];
    __syncthreads();

    ull acc[4][4];
#pragma unroll
    for (int r = 0; r < 4; r++)
#pragma unroll
        for (int cp = 0; cp < 4; cp++) acc[r][cp] = 0ULL;

#pragma unroll 4
    for (int k = 0; k < K; k++) {
        const float4 av = *((const float4*)(saT + k * 64 + r0));
        const ull A0 = dup2(av.x), A1 = dup2(av.y), A2r = dup2(av.z), A3 = dup2(av.w);
        const float* wr = sW + k * O + c0;
        const ulonglong2 W03 = *((const ulonglong2*)wr);
        const ulonglong2 W47 = *((const ulonglong2*)(wr + 4));
        fma2(acc[0][0], A0, W03.x);  fma2(acc[0][1], A0, W03.y);
        fma2(acc[0][2], A0, W47.x);  fma2(acc[0][3], A0, W47.y);
        fma2(acc[1][0], A1, W03.x);  fma2(acc[1][1], A1, W03.y);
        fma2(acc[1][2], A1, W47.x);  fma2(acc[1][3], A1, W47.y);
        fma2(acc[2][0], A2r, W03.x); fma2(acc[2][1], A2r, W03.y);
        fma2(acc[2][2], A2r, W47.x); fma2(acc[2][3], A2r, W47.y);
        fma2(acc[3][0], A3, W03.x);  fma2(acc[3][1], A3, W03.y);
        fma2(acc[3][2], A3, W47.x);  fma2(acc[3][3], A3, W47.y);
    }

    float bb[8];
#pragma unroll
    for (int c = 0; c < 8; c++) bb[c] = bias ? bias[c0 + c] : 0.f;

#pragma unroll
    for (int r = 0; r < 4; r++) {
        const int rgl = row0 + r0 + r;
        if (rgl >= nrows) continue;
        float y[8];
#pragma unroll
        for (int cp = 0; cp < 4; cp++) {
            const float2 f = unpack2(acc[r][cp]);
            y[2 * cp]     = f.x + bb[2 * cp];
            y[2 * cp + 1] = f.y + bb[2 * cp + 1];
        }
        float4* op = (float4*)(out + (size_t)rgl * O + c0);
        op[0] = make_float4(y[0], y[1], y[2], y[3]);
        op[1] = make_float4(y[4], y[5], y[6], y[7]);
    }
}

// ================= merged conv GEMM: c = x@W[0:64], d = x@W[64:128] ===========
// Optionally fuses the previous layer's update: x = softplus(x + ns*sc2 + sh2),
// written back to g_x (each block owns its rows exclusively -> race-free;
// deterministic across graph replays because g_x is rewritten by the embedding
// GEMM at the start of every kernel_launch).
__global__ void __launch_bounds__(256)
convgemm_kernel(float* __restrict__ x, const float* __restrict__ W,
                float* __restrict__ outc, float* __restrict__ outd,
                const float* __restrict__ ns)
{
    __shared__ float saT[64 * 64];    // 16KB  [k][r]
    __shared__ float sW[64 * 128];    // 32KB  [k][o]

    const int t  = threadIdx.x;
    const int rg = t / 16;
    const int cg = t % 16;
    const int r0 = rg * 4;
    const int c0 = cg * 8;
    const int row0 = blockIdx.x * 64;

    // A fill (+ fused update)
    for (int idx = t; idx < 64 * 16; idx += 256) {
        const int r  = idx / 16;
        const int kq = idx % 16;
        const int rgl = row0 + r;
        float4 v = make_float4(0.f, 0.f, 0.f, 0.f);
        if (rgl < NN) {
            v = *(((const float4*)(x + (size_t)rgl * AA)) + kq);
            if (ns) {
                const float4 nv = *(((const float4*)(ns + (size_t)rgl * AA)) + kq);
                const int a = 4 * kq;
                v.x = sp_f(v.x + nv.x * g_scale2[a + 0] + g_shift2[a + 0]);
                v.y = sp_f(v.y + nv.y * g_scale2[a + 1] + g_shift2[a + 1]);
                v.z = sp_f(v.z + nv.z * g_scale2[a + 2] + g_shift2[a + 2]);
                v.w = sp_f(v.w + nv.w * g_scale2[a + 3] + g_shift2[a + 3]);
                *(((float4*)(x + (size_t)rgl * AA)) + kq) = v;
            }
        }
        saT[(4 * kq + 0) * 64 + r] = v.x;
        saT[(4 * kq + 1) * 64 + r] = v.y;
        saT[(4 * kq + 2) * 64 + r] = v.z;
        saT[(4 * kq + 3) * 64 + r] = v.w;
    }

    for (int s = 0; s < 2; s++) {
        const float* Ws = W + (size_t)s * 64 * A2;
        float* outp = s ? outd : outc;
        for (int idx = t; idx < 64 * A2 / 4; idx += 256)
            ((float4*)sW)[idx] = ((const float4*)Ws)[idx];
        __syncthreads();

        ull acc[4][4];
#pragma unroll
        for (int r = 0; r < 4; r++)
#pragma unroll
            for (int cp = 0; cp < 4; cp++) acc[r][cp] = 0ULL;

#pragma unroll 4
        for (int k = 0; k < 64; k++) {
            const float4 av = *((const float4*)(saT + k * 64 + r0));
            const ull A0 = dup2(av.x), A1 = dup2(av.y), A2r = dup2(av.z), A3 = dup2(av.w);
            const float* wr = sW + k * A2 + c0;
            const ulonglong2 W03 = *((const ulonglong2*)wr);
            const ulonglong2 W47 = *((const ulonglong2*)(wr + 4));
            fma2(acc[0][0], A0, W03.x);  fma2(acc[0][1], A0, W03.y);
            fma2(acc[0][2], A0, W47.x);  fma2(acc[0][3], A0, W47.y);
            fma2(acc[1][0], A1, W03.x);  fma2(acc[1][1], A1, W03.y);
            fma2(acc[1][2], A1, W47.x);  fma2(acc[1][3], A1, W47.y);
            fma2(acc[2][0], A2r, W03.x); fma2(acc[2][1], A2r, W03.y);
            fma2(acc[2][2], A2r, W47.x); fma2(acc[2][3], A2r, W47.y);
            fma2(acc[3][0], A3, W03.x);  fma2(acc[3][1], A3, W03.y);
            fma2(acc[3][2], A3, W47.x);  fma2(acc[3][3], A3, W47.y);
        }

#pragma unroll
        for (int r = 0; r < 4; r++) {
            const int rgl = row0 + r0 + r;
            if (rgl >= NN) continue;
            float y[8];
#pragma unroll
            for (int cp = 0; cp < 4; cp++) {
                const float2 f = unpack2(acc[r][cp]);
                y[2 * cp]     = f.x;
                y[2 * cp + 1] = f.y;
            }
            float4* op = (float4*)(outp + (size_t)rgl * A2 + c0);
            op[0] = make_float4(y[0], y[1], y[2], y[3]);
            op[1] = make_float4(y[4], y[5], y[6], y[7]);
        }
        __syncthreads();
    }
}

// ---------------- zero BN stats ----------------
__global__ void zero_stats_kernel() {
    const int t = threadIdx.x;
    if (t < A2) { g_s1[t] = 0.0; g_q1[t] = 0.0; }
    if (t < AA) { g_s2[t] = 0.0; g_q2[t] = 0.0; }
}

// ================= gated: per-warp 12x128 edge GEMM + assemble =================
__global__ void __launch_bounds__(128, 3)
gated_kernel(const int* __restrict__ nbr_idx,
             const float* __restrict__ W3, const float* __restrict__ bias)
{
    __shared__ __align__(16) float sW3[NBRF * A2];          // [f][o]
    __shared__ __align__(16) float s_nf[2][4][NFE];         // [buf][slot][f*12+m]
    __shared__ int s_idx[2][4][MM];

    const int t    = threadIdx.x;
    const int slot = t >> 5;
    const int u    = t & 31;
    const int col0 = 4 * u;
    const int atom0 = blockIdx.x * 16;

    for (int i = t; i < NBRF * A2; i += 128) sW3[i] = W3[i];

    // stage batch 0 (half -> float during copy; layout already [f][m])
    {
#pragma unroll
        for (int sl = 0; sl < 4; sl++) {
            const int n = atom0 + sl;
            if (n >= NN) break;
            const unsigned* src = (const unsigned*)g_nfh + (size_t)n * (NFE / 2);
            float* dst = s_nf[0][sl];
            for (int e = t; e < NFE / 2; e += 128) {
                const unsigned v = src[e];
                *((float2*)(dst + 2 * e)) = __half22float2(*(__half2*)&v);
            }
        }
        if (t < 4 * MM && atom0 + t / MM < NN)
            s_idx[0][t / MM][t % MM] = nbr_idx[(atom0 + t / MM) * MM + t % MM];
    }

    const float4 bvec = *((const float4*)(bias + col0));
    float sc[4] = {0.f, 0.f, 0.f, 0.f}, qc[4] = {0.f, 0.f, 0.f, 0.f};
    __syncthreads();

    for (int b = 0; b < 4; b++) {
        const int cur = b & 1, nxt = cur ^ 1;
        const int n = atom0 + b * 4 + slot;

        float4 dm[MM];
#pragma unroll
        for (int m = 0; m < MM; m++)
            dm[m] = *((const float4*)(g_d + (size_t)s_idx[cur][slot][m] * A2 + col0));
        const float4 cv = *((const float4*)(g_c + (size_t)n * A2 + col0));
        float cb[4] = {cv.x + bvec.x, cv.y + bvec.y, cv.z + bvec.z, cv.w + bvec.w};

        if (b < 3) {
            const int na0 = atom0 + (b + 1) * 4;
#pragma unroll
            for (int sl = 0; sl < 4; sl++) {
                const int n2 = na0 + sl;
                if (n2 >= NN) break;
                const unsigned* src = (const unsigned*)g_nfh + (size_t)n2 * (NFE / 2);
                float* dst = s_nf[nxt][sl];
                for (int e = t; e < NFE / 2; e += 128) {
                    const unsigned v = src[e];
                    *((float2*)(dst + 2 * e)) = __half22float2(*(__half2*)&v);
                }
            }
            if (t < 4 * MM && na0 + t / MM < NN)
                s_idx[nxt][t / MM][t % MM] = nbr_idx[(na0 + t / MM) * MM + t % MM];
        }

        ull acc[6][4];
#pragma unroll
        for (int mp = 0; mp < 6; mp++)
#pragma unroll
            for (int c = 0; c < 4; c++) acc[mp][c] = 0ULL;

        const float* nfb = s_nf[cur][slot];
#pragma unroll 1
        for (int f = 0; f < NBRF; f++) {
            const float4 w4 = *((const float4*)(sW3 + f * A2 + col0));
            const ull wd0 = dup2(w4.x), wd1 = dup2(w4.y), wd2 = dup2(w4.z), wd3 = dup2(w4.w);
            const float* row = nfb + f * MM;
            const ulonglong2 pa = *((const ulonglong2*)row);
            const ulonglong2 pb = *((const ulonglong2*)(row + 4));
            const ulonglong2 pc = *((const ulonglong2*)(row + 8));
            fma2(acc[0][0], pa.x, wd0); fma2(acc[0][1], pa.x, wd1);
            fma2(acc[0][2], pa.x, wd2); fma2(acc[0][3], pa.x, wd3);
            fma2(acc[1][0], pa.y, wd0); fma2(acc[1][1], pa.y, wd1);
            fma2(acc[1][2], pa.y, wd2); fma2(acc[1][3], pa.y, wd3);
            fma2(acc[2][0], pb.x, wd0); fma2(acc[2][1], pb.x, wd1);
            fma2(acc[2][2], pb.x, wd2); fma2(acc[2][3], pb.x, wd3);
            fma2(acc[3][0], pb.y, wd0); fma2(acc[3][1], pb.y, wd1);
            fma2(acc[3][2], pb.y, wd2); fma2(acc[3][3], pb.y, wd3);
            fma2(acc[4][0], pc.x, wd0); fma2(acc[4][1], pc.x, wd1);
            fma2(acc[4][2], pc.x, wd2); fma2(acc[4][3], pc.x, wd3);
            fma2(acc[5][0], pc.y, wd0); fma2(acc[5][1], pc.y, wd1);
            fma2(acc[5][2], pc.y, wd2); fma2(acc[5][3], pc.y, wd3);
        }

        __half2* gout = g_gatedh + (size_t)n * (6 * A2) + col0;
#pragma unroll
        for (int mp = 0; mp < 6; mp++) {
            const float* d0 = (const float*)&dm[2 * mp];
            const float* d1 = (const float*)&dm[2 * mp + 1];
            uint4 st;
            unsigned* stv = (unsigned*)&st;
#pragma unroll
            for (int c = 0; c < 4; c++) {
                const float2 e2 = unpack2(acc[mp][c]);
                const float y0 = e2.x + cb[c] + d0[c];
                const float y1 = e2.y + cb[c] + d1[c];
                __half2 h = __floats2half2_rn(y0, y1);
                stv[c] = *(unsigned*)&h;
                sc[c] += y0 + y1;
                qc[c] += y0 * y0 + y1 * y1;
            }
            *((uint4*)(gout + mp * A2)) = st;
        }
        __syncthreads();
    }

    float* scr = (float*)&s_nf[0][0][0];
#pragma unroll
    for (int c = 0; c < 4; c++) {
        scr[slot * A2 + col0 + c]       = sc[c];
        scr[512 + slot * A2 + col0 + c] = qc[c];
    }
    __syncthreads();
    if (slot == 0) {
#pragma unroll
        for (int c = 0; c < 4; c++) {
            const int o = col0 + c;
            const float ts = scr[o] + scr[A2 + o] + scr[2 * A2 + o] + scr[3 * A2 + o];
            const float tq = scr[512 + o] + scr[512 + A2 + o] + scr[512 + 2 * A2 + o] + scr[512 + 3 * A2 + o];
            atomicAdd(&g_s1[o], (double)ts);
            atomicAdd(&g_q1[o], (double)tq);
        }
    }
}

__global__ void finalize1_kernel(const float* __restrict__ g1, const float* __restrict__ b1) {
    const int o = threadIdx.x;
    const double cnt = (double)NN * MM;
    const double mean = g_s1[o] / cnt;
    const double var  = g_q1[o] / cnt - mean * mean;
    const float scale = g1[o] * rsqrtf((float)var + EPSL);
    g_scale1[o] = scale;
    g_shift1[o] = b1[o] - (float)mean * scale;
}

// ---------------- gatesum: vectorized uint4 loads, thread = 4 cols -------------
__global__ void gatesum_kernel() {
    __shared__ float ss[16][64], sq[16][64];
    const int t = threadIdx.x;
    const int slot = t >> 4;
    const int col0 = 4 * (t & 15);

    const float4 scf = *((const float4*)(g_scale1 + col0));
    const float4 shf = *((const float4*)(g_shift1 + col0));
    const float4 scc = *((const float4*)(g_scale1 + 64 + col0));
    const float4 shc = *((const float4*)(g_shift1 + 64 + col0));
    const float scfv[4] = {scf.x, scf.y, scf.z, scf.w};
    const float shfv[4] = {shf.x, shf.y, shf.z, shf.w};
    const float sccv[4] = {scc.x, scc.y, scc.z, scc.w};
    const float shcv[4] = {shc.x, shc.y, shc.z, shc.w};

    float sc[4] = {0.f, 0.f, 0.f, 0.f}, qc[4] = {0.f, 0.f, 0.f, 0.f};

    for (int i = 0; i < 4; i++) {
        const int n = blockIdx.x * 64 + slot * 4 + i;
        if (n >= NN) break;
        const uint4* gp = (const uint4*)(g_gatedh + (size_t)n * (6 * A2));
        float acc[4] = {0.f, 0.f, 0.f, 0.f};
#pragma unroll
        for (int mp = 0; mp < 6; mp++) {
            const uint4 uf = gp[(mp * A2 + col0) >> 2];
            const uint4 uc = gp[(mp * A2 + 64 + col0) >> 2];
            const unsigned* ufv = (const unsigned*)&uf;
            const unsigned* ucv = (const unsigned*)&uc;
#pragma unroll
            for (int c = 0; c < 4; c++) {
                const float2 fv = __half22float2(*(__half2*)&ufv[c]);
                const float2 cv = __half22float2(*(__half2*)&ucv[c]);
                const float yf0 = fv.x * scfv[c] + shfv[c];
                const float yf1 = fv.y * scfv[c] + shfv[c];
                const float yc0 = cv.x * sccv[c] + shcv[c];
                const float yc1 = cv.y * sccv[c] + shcv[c];
                acc[c] += sg_f(yf0) * sp_f(yc0) + sg_f(yf1) * sp_f(yc1);
            }
        }
        *((float4*)(g_ns + (size_t)n * AA + col0)) = make_float4(acc[0], acc[1], acc[2], acc[3]);
#pragma unroll
        for (int c = 0; c < 4; c++) { sc[c] += acc[c]; qc[c] += acc[c] * acc[c]; }
    }

#pragma unroll
    for (int c = 0; c < 4; c++) { ss[slot][col0 + c] = sc[c]; sq[slot][col0 + c] = qc[c]; }
    __syncthreads();
    if (t < 64) {
        float a = 0.f, b = 0.f;
#pragma unroll
        for (int s = 0; s < 16; s++) { a += ss[s][t]; b += sq[s][t]; }
        atomicAdd(&g_s2[t], (double)a);
        atomicAdd(&g_q2[t], (double)b);
    }
}

__global__ void finalize2_kernel(const float* __restrict__ g2, const float* __restrict__ b2) {
    const int a = threadIdx.x;
    const double cnt = (double)NN;
    const double mean = g_s2[a] / cnt;
    const double var  = g_q2[a] / cnt - mean * mean;
    const float scale = g2[a] * rsqrtf((float)var + EPSL);
    g_scale2[a] = scale;
    g_shift2[a] = b2[a] - (float)mean * scale;
}

// standalone update (last layer only; earlier layers fused into convgemm)
__global__ void update_kernel() {
    const int i = blockIdx.x * blockDim.x + threadIdx.x;
    if (i >= NN * AA) return;
    const int a = i & 63;
    const float v = g_x[i] + g_ns[i] * g_scale2[a] + g_shift2[a];
    g_x[i] = sp_f(v);
}

// ---------------- fused pool + head (crystals are 100 contiguous atoms) --------
__global__ void head2_kernel(const float* __restrict__ fc_W, const float* __restrict__ fc_b,
                             const float* __restrict__ out_W, const float* __restrict__ out_b,
                             float* __restrict__ out)
{
    __shared__ float sred[2][64];
    __shared__ float spm[64];
    __shared__ float red[128];
    const int c = blockIdx.x, t = threadIdx.x;
    const int a = t & 63, half = t >> 6;

    float s = 0.f;
    const int r0 = c * 100 + half * 50;
    for (int i = 0; i < 50; i++) s += g_x[(r0 + i) * 64 + a];
    sred[half][a] = s;
    __syncthreads();
    if (t < 64) spm[t] = sp_f((sred[0][t] + sred[1][t]) * 0.01f);
    __syncthreads();

    float h = fc_b[t];
#pragma unroll
    for (int aa = 0; aa < 64; aa++) h += spm[aa] * fc_W[aa * HH + t];
    red[t] = sp_f(h) * out_W[t];
    __syncthreads();
    for (int sft = 64; sft > 0; sft >>= 1) {
        if (t < sft) red[t] += red[t + sft];
        __syncthreads();
    }
    if (t == 0) out[c] = red[0] + out_b[0];
}

// ---------------- host orchestration ----------------
extern "C" void kernel_launch(void* const* d_in, const int* in_sizes, int n_in,
                              void* d_out, int out_size)
{
    const float* atom_fea = (const float*)d_in[0];
    const float* nbr_fea  = (const float*)d_in[1];
    const int*   nbr_idx  = (const int*)  d_in[2];
    const float* emb_W    = (const float*)d_in[4];
    const float* emb_b    = (const float*)d_in[5];
    const float* conv_W   = (const float*)d_in[6];
    const float* conv_b   = (const float*)d_in[7];
    const float* bn1_g    = (const float*)d_in[8];
    const float* bn1_b    = (const float*)d_in[9];
    const float* bn2_g    = (const float*)d_in[10];
    const float* bn2_b    = (const float*)d_in[11];
    const float* fc_W     = (const float*)d_in[12];
    const float* fc_b     = (const float*)d_in[13];
    const float* out_W    = (const float*)d_in[14];
    const float* out_b    = (const float*)d_in[15];
    float* out = (float*)d_out;

    float *px, *pc, *pd, *pns;
    cudaGetSymbolAddress((void**)&px, g_x);
    cudaGetSymbolAddress((void**)&pc, g_c);
    cudaGetSymbolAddress((void**)&pd, g_d);
    cudaGetSymbolAddress((void**)&pns, g_ns);

    const int gemmBlocks = (NN + 63) / 64;
    const size_t smemE = (size_t)ORIGF * 64 * 4 + (size_t)ORIGF * AA * 4;  // 46KB

    nf2half_kernel<<<(NN + 7) / 8, 128>>>(nbr_fea);
    gemmT_kernel<ORIGF, AA><<<gemmBlocks, 128, smemE>>>(atom_fea, emb_W, emb_b, px, NN);

    for (int i = 0; i < NCONVL; i++) {
        const float* Wl = conv_W + (size_t)i * (2 * AA + NBRF) * A2;
        zero_stats_kernel<<<1, 128>>>();
        convgemm_kernel<<<gemmBlocks, 256>>>(px, Wl, pc, pd, (i > 0) ? pns : nullptr);
        gated_kernel<<<NN / 16, 128>>>(nbr_idx, Wl + 128 * A2, conv_b + i * A2);
        finalize1_kernel<<<1, A2>>>(bn1_g + i * A2, bn1_b + i * A2);
        gatesum_kernel<<<(NN + 63) / 64, 256>>>();
        finalize2_kernel<<<1, AA>>>(bn2_g + i * AA, bn2_b + i * AA);
    }

    update_kernel<<<(NN * AA + 255) / 256, 256>>>();
    head2_kernel<<<NC0, 128>>>(fc_W, fc_b, out_W, out_b, out);
}

// round 10
// speedup vs baseline: 2.2933x; 1.4982x over previous
#include <cuda_runtime.h>
#include <cuda_fp16.h>
#include <math.h>

#define NN   100000
#define MM   12
#define ORIGF 92
#define NBRF 41
#define AA   64
#define A2   128
#define HH   128
#define NCONVL 3
#define NC0  1000
#define EPSL 1e-5f
#define NE   (NN * MM)          // 1.2M edges
#define KP   48                 // padded K for edge GEMM

typedef unsigned long long ull;

// ---------------- scratch ----------------
__device__ float   g_x[NN * AA];
__device__ __half  g_ch[NN * A2];                   // c fp16
__device__ __half  g_dh[NN * A2];                   // d fp16
__device__ __half  g_nfe[(size_t)NE * KP];          // edge features fp16, [e][48] zero-padded
__device__ uint2   g_w3f[NCONVL][3 * 16 * 32];      // W3 in B-fragment layout per layer
__device__ __half  g_gatedh[(size_t)NE * A2];       // pre-BN gated, edge-major [e][128]
__device__ float   g_ns[NN * AA];
__device__ double  g_s1[A2], g_q1[A2];
__device__ double  g_s2[AA], g_q2[AA];
__device__ float   g_scale1[A2], g_shift1[A2];
__device__ float   g_scale2[AA], g_shift2[AA];

// ---------------- f32x2 helpers (for scalar GEMMs) ----------------
__device__ __forceinline__ ull pack2(float lo, float hi) {
    ull r; asm("mov.b64 %0, {%1, %2};" : "=l"(r) : "f"(lo), "f"(hi)); return r;
}
__device__ __forceinline__ ull dup2(float v) { return pack2(v, v); }
__device__ __forceinline__ void fma2(ull& d, ull a, ull b) {
    asm("fma.rn.f32x2 %0, %1, %2, %0;" : "+l"(d) : "l"(a), "l"(b));
}
__device__ __forceinline__ float2 unpack2(ull v) {
    float2 f; asm("mov.b64 {%0, %1}, %2;" : "=f"(f.x), "=f"(f.y) : "l"(v)); return f;
}

__device__ __forceinline__ unsigned h2_to_u(__half2 h) { return *(unsigned*)&h; }
__device__ __forceinline__ float2 u_to_f2(unsigned u) { return __half22float2(*(__half2*)&u); }

// ---------------- activations ----------------
__device__ __forceinline__ float sp_f(float x) {
    return fmaxf(x, 0.f) + __logf(1.f + __expf(-fabsf(x)));
}
__device__ __forceinline__ float sg_f(float x) {
    return __fdividef(1.f, 1.f + __expf(-x));
}

// ---------------- HMMA m16n8k16 row.col f16f16 -> f32 ----------------
__device__ __forceinline__ void mma16816(float& c0, float& c1, float& c2, float& c3,
                                         unsigned a0, unsigned a1, unsigned a2, unsigned a3,
                                         unsigned b0, unsigned b1) {
    asm volatile(
        "mma.sync.aligned.m16n8k16.row.col.f32.f16.f16.f32 "
        "{%0,%1,%2,%3}, {%4,%5,%6,%7}, {%8,%9}, {%0,%1,%2,%3};\n"
        : "+f"(c0), "+f"(c1), "+f"(c2), "+f"(c3)
        : "r"(a0), "r"(a1), "r"(a2), "r"(a3), "r"(b0), "r"(b1));
}

// ================= prep: nbr_fea -> edge-major fp16, padded to 48 ==============
__global__ void nfe_prep(const float* __restrict__ nbr_fea) {
    const unsigned j = blockIdx.x * 256 + threadIdx.x;   // half2 slot
    if (j >= (unsigned)NE * (KP / 2)) return;
    const unsigned e = j / (KP / 2);
    const int kk = (int)(j % (KP / 2)) * 2;
    const float v0 = (kk     < NBRF) ? nbr_fea[(size_t)e * NBRF + kk]     : 0.f;
    const float v1 = (kk + 1 < NBRF) ? nbr_fea[(size_t)e * NBRF + kk + 1] : 0.f;
    ((unsigned*)g_nfe)[j] = h2_to_u(__floats2half2_rn(v0, v1));
}

// ================= prep: W3 -> B-fragment layout (all layers) ==================
__global__ void w3f_prep(const float* __restrict__ conv_W) {
    const int idx = blockIdx.x * 256 + threadIdx.x;      // over 3*3*16*32
    if (idx >= NCONVL * 3 * 16 * 32) return;
    const int lane  = idx & 31;
    const int nt    = (idx >> 5) & 15;
    const int ks    = (idx >> 9) % 3;
    const int layer = idx / (3 * 16 * 32);
    const float* W3 = conv_W + (size_t)layer * (2 * AA + NBRF) * A2 + 128 * A2;  // [41][128]
    const int n  = nt * 8 + (lane >> 2);
    const int k0 = ks * 16 + (lane & 3) * 2;
    auto gw = [&](int k) -> float { return (k < NBRF) ? W3[k * A2 + n] : 0.f; };
    uint2 b;
    b.x = h2_to_u(__floats2half2_rn(gw(k0),     gw(k0 + 1)));
    b.y = h2_to_u(__floats2half2_rn(gw(k0 + 8), gw(k0 + 9)));
    g_w3f[layer][idx % (3 * 16 * 32)] = b;
}

// ================= embedding GEMM (once): g_x = atom_fea @ emb_W + b ===========
template <int K, int O>
__global__ void __launch_bounds__(256)
gemmT_kernel(const float* __restrict__ in, const float* __restrict__ W,
             const float* __restrict__ bias, float* __restrict__ out, int nrows)
{
    extern __shared__ char dsm[];
    float* saT = (float*)dsm;
    float* sW  = (float*)(dsm + (size_t)K * 64 * 4);

    const int nt = blockDim.x;
    const int t  = threadIdx.x;
    const int CG = O / 8;
    const int rg = t / CG;
    const int cg = t % CG;
    const int r0 = rg * 4;
    const int c0 = cg * 8;
    const int row0 = blockIdx.x * 64;

    for (int idx = t; idx < 64 * (K / 4); idx += nt) {
        const int r  = idx / (K / 4);
        const int kq = idx % (K / 4);
        float4 v = make_float4(0.f, 0.f, 0.f, 0.f);
        if (row0 + r < nrows) v = *(((const float4*)(in + (size_t)(row0 + r) * K)) + kq);
        saT[(4 * kq + 0) * 64 + r] = v.x;
        saT[(4 * kq + 1) * 64 + r] = v.y;
        saT[(4 * kq + 2) * 64 + r] = v.z;
        saT[(4 * kq + 3) * 64 + r] = v.w;
    }
    for (int idx = t; idx < K * O / 4; idx += nt)
        ((float4*)sW)[idx] = ((const float4*)W)[idx];
    __syncthreads();

    ull acc[4][4];
#pragma unroll
    for (int r = 0; r < 4; r++)
#pragma unroll
        for (int cp = 0; cp < 4; cp++) acc[r][cp] = 0ULL;

#pragma unroll 4
    for (int k = 0; k < K; k++) {
        const float4 av = *((const float4*)(saT + k * 64 + r0));
        const ull A0 = dup2(av.x), A1 = dup2(av.y), A2r = dup2(av.z), A3 = dup2(av.w);
        const float* wr = sW + k * O + c0;
        const ulonglong2 W03 = *((const ulonglong2*)wr);
        const ulonglong2 W47 = *((const ulonglong2*)(wr + 4));
        fma2(acc[0][0], A0, W03.x);  fma2(acc[0][1], A0, W03.y);
        fma2(acc[0][2], A0, W47.x);  fma2(acc[0][3], A0, W47.y);
        fma2(acc[1][0], A1, W03.x);  fma2(acc[1][1], A1, W03.y);
        fma2(acc[1][2], A1, W47.x);  fma2(acc[1][3], A1, W47.y);
        fma2(acc[2][0], A2r, W03.x); fma2(acc[2][1], A2r, W03.y);
        fma2(acc[2][2], A2r, W47.x); fma2(acc[2][3], A2r, W47.y);
        fma2(acc[3][0], A3, W03.x);  fma2(acc[3][1], A3, W03.y);
        fma2(acc[3][2], A3, W47.x);  fma2(acc[3][3], A3, W47.y);
    }

    float bb[8];
#pragma unroll
    for (int c = 0; c < 8; c++) bb[c] = bias ? bias[c0 + c] : 0.f;

#pragma unroll
    for (int r = 0; r < 4; r++) {
        const int rgl = row0 + r0 + r;
        if (rgl >= nrows) continue;
        float y[8];
#pragma unroll
        for (int cp = 0; cp < 4; cp++) {
            const float2 f = unpack2(acc[r][cp]);
            y[2 * cp]     = f.x + bb[2 * cp];
            y[2 * cp + 1] = f.y + bb[2 * cp + 1];
        }
        float4* op = (float4*)(out + (size_t)rgl * O + c0);
        op[0] = make_float4(y[0], y[1], y[2], y[3]);
        op[1] = make_float4(y[4], y[5], y[6], y[7]);
    }
}

// ================= merged conv GEMM -> fp16 outputs c,d ========================
__global__ void __launch_bounds__(256)
convgemm_kernel(float* __restrict__ x, const float* __restrict__ W,
                __half* __restrict__ outc, __half* __restrict__ outd,
                const float* __restrict__ ns)
{
    __shared__ float saT[64 * 64];
    __shared__ float sW[64 * 128];

    const int t  = threadIdx.x;
    const int rg = t / 16;
    const int cg = t % 16;
    const int r0 = rg * 4;
    const int c0 = cg * 8;
    const int row0 = blockIdx.x * 64;

    for (int idx = t; idx < 64 * 16; idx += 256) {
        const int r  = idx / 16;
        const int kq = idx % 16;
        const int rgl = row0 + r;
        float4 v = make_float4(0.f, 0.f, 0.f, 0.f);
        if (rgl < NN) {
            v = *(((const float4*)(x + (size_t)rgl * AA)) + kq);
            if (ns) {
                const float4 nv = *(((const float4*)(ns + (size_t)rgl * AA)) + kq);
                const int a = 4 * kq;
                v.x = sp_f(v.x + nv.x * g_scale2[a + 0] + g_shift2[a + 0]);
                v.y = sp_f(v.y + nv.y * g_scale2[a + 1] + g_shift2[a + 1]);
                v.z = sp_f(v.z + nv.z * g_scale2[a + 2] + g_shift2[a + 2]);
                v.w = sp_f(v.w + nv.w * g_scale2[a + 3] + g_shift2[a + 3]);
                *(((float4*)(x + (size_t)rgl * AA)) + kq) = v;
            }
        }
        saT[(4 * kq + 0) * 64 + r] = v.x;
        saT[(4 * kq + 1) * 64 + r] = v.y;
        saT[(4 * kq + 2) * 64 + r] = v.z;
        saT[(4 * kq + 3) * 64 + r] = v.w;
    }

    for (int s = 0; s < 2; s++) {
        const float* Ws = W + (size_t)s * 64 * A2;
        __half* outp = s ? outd : outc;
        for (int idx = t; idx < 64 * A2 / 4; idx += 256)
            ((float4*)sW)[idx] = ((const float4*)Ws)[idx];
        __syncthreads();

        ull acc[4][4];
#pragma unroll
        for (int r = 0; r < 4; r++)
#pragma unroll
            for (int cp = 0; cp < 4; cp++) acc[r][cp] = 0ULL;

#pragma unroll 4
        for (int k = 0; k < 64; k++) {
            const float4 av = *((const float4*)(saT + k * 64 + r0));
            const ull A0 = dup2(av.x), A1 = dup2(av.y), A2r = dup2(av.z), A3 = dup2(av.w);
            const float* wr = sW + k * A2 + c0;
            const ulonglong2 W03 = *((const ulonglong2*)wr);
            const ulonglong2 W47 = *((const ulonglong2*)(wr + 4));
            fma2(acc[0][0], A0, W03.x);  fma2(acc[0][1], A0, W03.y);
            fma2(acc[0][2], A0, W47.x);  fma2(acc[0][3], A0, W47.y);
            fma2(acc[1][0], A1, W03.x);  fma2(acc[1][1], A1, W03.y);
            fma2(acc[1][2], A1, W47.x);  fma2(acc[1][3], A1, W47.y);
            fma2(acc[2][0], A2r, W03.x); fma2(acc[2][1], A2r, W03.y);
            fma2(acc[2][2], A2r, W47.x); fma2(acc[2][3], A2r, W47.y);
            fma2(acc[3][0], A3, W03.x);  fma2(acc[3][1], A3, W03.y);
            fma2(acc[3][2], A3, W47.x);  fma2(acc[3][3], A3, W47.y);
        }

#pragma unroll
        for (int r = 0; r < 4; r++) {
            const int rgl = row0 + r0 + r;
            if (rgl >= NN) continue;
            uint4 st;
            unsigned* stv = (unsigned*)&st;
#pragma unroll
            for (int cp = 0; cp < 4; cp++) {
                const float2 f = unpack2(acc[r][cp]);
                stv[cp] = h2_to_u(__floats2half2_rn(f.x, f.y));
            }
            *((uint4*)(outp + (size_t)rgl * A2 + c0)) = st;
        }
        __syncthreads();
    }
}

// ---------------- zero BN stats ----------------
__global__ void zero_stats_kernel() {
    const int t = threadIdx.x;
    if (t < A2) { g_s1[t] = 0.0; g_q1[t] = 0.0; }
    if (t < AA) { g_s2[t] = 0.0; g_q2[t] = 0.0; }
}

// ================= gated via HMMA: y[e,128] = nfe[e,:]@W3 + c[n]+d[idx]+b ======
// 128 threads (4 warps); 192 edges/block in 3 passes of 64; warp = 16-edge strip.
__global__ void __launch_bounds__(128, 4)
gatedmma_kernel(const int* __restrict__ nbr_idx,
                const uint2* __restrict__ w3f, const float* __restrict__ bias)
{
    __shared__ __align__(16) uint2  sB[3 * 16 * 32];     // 12KB  B fragments
    __shared__ __align__(16) __half scd[64 * 136];       // 17KB  cd / y buffer (pad 8)

    const int t    = threadIdx.x;
    const int w    = t >> 5;
    const int lane = t & 31;
    const int g    = lane >> 2;
    const int i    = lane & 3;

    for (int idx = t; idx < 3 * 16 * 32; idx += 128) sB[idx] = w3f[idx];
    const float4 bias4 = *((const float4*)(bias + lane * 4));

    float s_acc = 0.f, q_acc = 0.f;
    const unsigned eblock = blockIdx.x * 192;
    __syncthreads();

    for (int pass = 0; pass < 3; pass++) {
        const unsigned e0 = eblock + pass * 64;

        // ---- stage cd = c[n] + d[idx] + bias into scd (warp w: edges w*16..+15)
        for (int k = 0; k < 16; k++) {
            const unsigned e = e0 + w * 16 + k;
            const unsigned n = e / MM;
            const int j = nbr_idx[e];
            const uint2 cu = ((const uint2*)g_ch)[(size_t)n * 32 + lane];
            const uint2 du = ((const uint2*)g_dh)[(size_t)j * 32 + lane];
            const float2 ca = u_to_f2(cu.x), cb2 = u_to_f2(cu.y);
            const float2 da = u_to_f2(du.x), db2 = u_to_f2(du.y);
            const float v0 = ca.x + da.x + bias4.x;
            const float v1 = ca.y + da.y + bias4.y;
            const float v2 = cb2.x + db2.x + bias4.z;
            const float v3 = cb2.y + db2.y + bias4.w;
            unsigned* dst = (unsigned*)(scd + (w * 16 + k) * 136 + lane * 4);
            dst[0] = h2_to_u(__floats2half2_rn(v0, v1));
            dst[1] = h2_to_u(__floats2half2_rn(v2, v3));
        }
        __syncthreads();

        // ---- mma: warp strip of 16 edges x 128 cols
        float acc[16][4];
#pragma unroll
        for (int nt = 0; nt < 16; nt++)
#pragma unroll
            for (int c = 0; c < 4; c++) acc[nt][c] = 0.f;

        const unsigned* Ag = (const unsigned*)g_nfe;
        const unsigned arow0 = (e0 + w * 16 + g) * (KP / 2);
        const unsigned arow1 = arow0 + 8 * (KP / 2);

#pragma unroll
        for (int ks = 0; ks < 3; ks++) {
            const unsigned a0 = Ag[arow0 + ks * 8 + i];
            const unsigned a1 = Ag[arow1 + ks * 8 + i];
            const unsigned a2 = Ag[arow0 + ks * 8 + i + 4];
            const unsigned a3 = Ag[arow1 + ks * 8 + i + 4];
#pragma unroll
            for (int nt = 0; nt < 16; nt++) {
                const uint2 b = sB[(ks * 16 + nt) * 32 + lane];
                mma16816(acc[nt][0], acc[nt][1], acc[nt][2], acc[nt][3],
                         a0, a1, a2, a3, b.x, b.y);
            }
        }

        // ---- y = acc + cd, write back into scd (same slots this thread owns)
        const int r0 = w * 16 + g, r1 = r0 + 8;
#pragma unroll
        for (int nt = 0; nt < 16; nt++) {
            unsigned* p0 = (unsigned*)(scd + r0 * 136 + nt * 8 + i * 2);
            unsigned* p1 = (unsigned*)(scd + r1 * 136 + nt * 8 + i * 2);
            const float2 cd0 = u_to_f2(*p0);
            const float2 cd1 = u_to_f2(*p1);
            *p0 = h2_to_u(__floats2half2_rn(acc[nt][0] + cd0.x, acc[nt][1] + cd0.y));
            *p1 = h2_to_u(__floats2half2_rn(acc[nt][2] + cd1.x, acc[nt][3] + cd1.y));
        }
        __syncthreads();

        // ---- stats (thread t = column t) + coalesced store to g_gatedh
        for (int r = 0; r < 64; r++) {
            const float v = __half2float(scd[r * 136 + t]);
            s_acc += v; q_acc += v * v;
        }
        for (int idx = t; idx < 64 * 16; idx += 128) {
            const int r = idx >> 4, ui = idx & 15;
            const uint4 vv = *((const uint4*)(scd + r * 136 + ui * 8));
            *((uint4*)(g_gatedh + (size_t)(e0 + r) * A2 + ui * 8)) = vv;
        }
        __syncthreads();
    }

    atomicAdd(&g_s1[t], (double)s_acc);
    atomicAdd(&g_q1[t], (double)q_acc);
}

__global__ void finalize1_kernel(const float* __restrict__ g1, const float* __restrict__ b1) {
    const int o = threadIdx.x;
    const double cnt = (double)NN * MM;
    const double mean = g_s1[o] / cnt;
    const double var  = g_q1[o] / cnt - mean * mean;
    const float scale = g1[o] * rsqrtf((float)var + EPSL);
    g_scale1[o] = scale;
    g_shift1[o] = b1[o] - (float)mean * scale;
}

// ---------------- gatesum (edge-major layout) ----------------
__global__ void gatesum_kernel() {
    __shared__ float ss[16][64], sq[16][64];
    const int t = threadIdx.x;
    const int slot = t >> 4;
    const int col0 = 4 * (t & 15);

    const float4 scf = *((const float4*)(g_scale1 + col0));
    const float4 shf = *((const float4*)(g_shift1 + col0));
    const float4 scc = *((const float4*)(g_scale1 + 64 + col0));
    const float4 shc = *((const float4*)(g_shift1 + 64 + col0));
    const float scfv[4] = {scf.x, scf.y, scf.z, scf.w};
    const float shfv[4] = {shf.x, shf.y, shf.z, shf.w};
    const float sccv[4] = {scc.x, scc.y, scc.z, scc.w};
    const float shcv[4] = {shc.x, shc.y, shc.z, shc.w};

    float sc[4] = {0.f, 0.f, 0.f, 0.f}, qc[4] = {0.f, 0.f, 0.f, 0.f};

    for (int i2 = 0; i2 < 4; i2++) {
        const int n = blockIdx.x * 64 + slot * 4 + i2;
        if (n >= NN) break;
        float acc[4] = {0.f, 0.f, 0.f, 0.f};
#pragma unroll
        for (int m = 0; m < MM; m++) {
            const __half* ge = g_gatedh + (size_t)(n * MM + m) * A2;
            const uint2 uf = *((const uint2*)(ge + col0));
            const uint2 uc = *((const uint2*)(ge + 64 + col0));
            const float2 f0 = u_to_f2(uf.x), f1 = u_to_f2(uf.y);
            const float2 c0 = u_to_f2(uc.x), c1 = u_to_f2(uc.y);
            acc[0] += sg_f(f0.x * scfv[0] + shfv[0]) * sp_f(c0.x * sccv[0] + shcv[0]);
            acc[1] += sg_f(f0.y * scfv[1] + shfv[1]) * sp_f(c0.y * sccv[1] + shcv[1]);
            acc[2] += sg_f(f1.x * scfv[2] + shfv[2]) * sp_f(c1.x * sccv[2] + shcv[2]);
            acc[3] += sg_f(f1.y * scfv[3] + shfv[3]) * sp_f(c1.y * sccv[3] + shcv[3]);
        }
        *((float4*)(g_ns + (size_t)n * AA + col0)) = make_float4(acc[0], acc[1], acc[2], acc[3]);
#pragma unroll
        for (int c = 0; c < 4; c++) { sc[c] += acc[c]; qc[c] += acc[c] * acc[c]; }
    }

#pragma unroll
    for (int c = 0; c < 4; c++) { ss[slot][col0 + c] = sc[c]; sq[slot][col0 + c] = qc[c]; }
    __syncthreads();
    if (t < 64) {
        float a = 0.f, b = 0.f;
#pragma unroll
        for (int s = 0; s < 16; s++) { a += ss[s][t]; b += sq[s][t]; }
        atomicAdd(&g_s2[t], (double)a);
        atomicAdd(&g_q2[t], (double)b);
    }
}

__global__ void finalize2_kernel(const float* __restrict__ g2, const float* __restrict__ b2) {
    const int a = threadIdx.x;
    const double cnt = (double)NN;
    const double mean = g_s2[a] / cnt;
    const double var  = g_q2[a] / cnt - mean * mean;
    const float scale = g2[a] * rsqrtf((float)var + EPSL);
    g_scale2[a] = scale;
    g_shift2[a] = b2[a] - (float)mean * scale;
}

__global__ void update_kernel() {
    const int i = blockIdx.x * blockDim.x + threadIdx.x;
    if (i >= NN * AA) return;
    const int a = i & 63;
    const float v = g_x[i] + g_ns[i] * g_scale2[a] + g_shift2[a];
    g_x[i] = sp_f(v);
}

// ---------------- fused pool + head ----------------
__global__ void head2_kernel(const float* __restrict__ fc_W, const float* __restrict__ fc_b,
                             const float* __restrict__ out_W, const float* __restrict__ out_b,
                             float* __restrict__ out)
{
    __shared__ float sred[2][64];
    __shared__ float spm[64];
    __shared__ float red[128];
    const int c = blockIdx.x, t = threadIdx.x;
    const int a = t & 63, half = t >> 6;

    float s = 0.f;
    const int r0 = c * 100 + half * 50;
    for (int i = 0; i < 50; i++) s += g_x[(r0 + i) * 64 + a];
    sred[half][a] = s;
    __syncthreads();
    if (t < 64) spm[t] = sp_f((sred[0][t] + sred[1][t]) * 0.01f);
    __syncthreads();

    float h = fc_b[t];
#pragma unroll
    for (int aa = 0; aa < 64; aa++) h += spm[aa] * fc_W[aa * HH + t];
    red[t] = sp_f(h) * out_W[t];
    __syncthreads();
    for (int sft = 64; sft > 0; sft >>= 1) {
        if (t < sft) red[t] += red[t + sft];
        __syncthreads();
    }
    if (t == 0) out[c] = red[0] + out_b[0];
}

// ---------------- host orchestration ----------------
extern "C" void kernel_launch(void* const* d_in, const int* in_sizes, int n_in,
                              void* d_out, int out_size)
{
    const float* atom_fea = (const float*)d_in[0];
    const float* nbr_fea  = (const float*)d_in[1];
    const int*   nbr_idx  = (const int*)  d_in[2];
    const float* emb_W    = (const float*)d_in[4];
    const float* emb_b    = (const float*)d_in[5];
    const float* conv_W   = (const float*)d_in[6];
    const float* conv_b   = (const float*)d_in[7];
    const float* bn1_g    = (const float*)d_in[8];
    const float* bn1_b    = (const float*)d_in[9];
    const float* bn2_g    = (const float*)d_in[10];
    const float* bn2_b    = (const float*)d_in[11];
    const float* fc_W     = (const float*)d_in[12];
    const float* fc_b     = (const float*)d_in[13];
    const float* out_W    = (const float*)d_in[14];
    const float* out_b    = (const float*)d_in[15];
    float* out = (float*)d_out;

    float *px, *pns;
    __half *pc, *pd;
    uint2 *pw3f;
    cudaGetSymbolAddress((void**)&px, g_x);
    cudaGetSymbolAddress((void**)&pc, g_ch);
    cudaGetSymbolAddress((void**)&pd, g_dh);
    cudaGetSymbolAddress((void**)&pns, g_ns);
    cudaGetSymbolAddress((void**)&pw3f, g_w3f);

    const int gemmBlocks = (NN + 63) / 64;
    const size_t smemE = (size_t)ORIGF * 64 * 4 + (size_t)ORIGF * AA * 4;  // 46KB

    nfe_prep<<<(NE * (KP / 2) + 255) / 256, 256>>>(nbr_fea);
    w3f_prep<<<(NCONVL * 3 * 16 * 32 + 255) / 256, 256>>>(conv_W);
    gemmT_kernel<ORIGF, AA><<<gemmBlocks, 128, smemE>>>(atom_fea, emb_W, emb_b, px, NN);

    for (int i = 0; i < NCONVL; i++) {
        const float* Wl = conv_W + (size_t)i * (2 * AA + NBRF) * A2;
        zero_stats_kernel<<<1, 128>>>();
        convgemm_kernel<<<gemmBlocks, 256>>>(px, Wl, pc, pd, (i > 0) ? pns : nullptr);
        gatedmma_kernel<<<NE / 192, 128>>>(nbr_idx, pw3f + (size_t)i * (3 * 16 * 32),
                                           conv_b + i * A2);
        finalize1_kernel<<<1, A2>>>(bn1_g + i * A2, bn1_b + i * A2);
        gatesum_kernel<<<(NN + 63) / 64, 256>>>();
        finalize2_kernel<<<1, AA>>>(bn2_g + i * AA, bn2_b + i * AA);
    }

    update_kernel<<<(NN * AA + 255) / 256, 256>>>();
    head2_kernel<<<NC0, 128>>>(fc_W, fc_b, out_W, out_b, out);
}